// round 8
// baseline (speedup 1.0000x reference)
#include <cuda_runtime.h>
#include <cuda_bf16.h>
#include <cstdint>
#include <math.h>

// Problem constants
#define BB   4
#define SS   2048
#define EE   1024
#define HHN  16
#define DKH  64
#define FFD  4096
#define MR   (BB*SS)   /* 8192 rows */

typedef __nv_bfloat16 bf16;

// ---------------------------------------------------------------------------
// Scratch (static __device__ arrays)
// ---------------------------------------------------------------------------
__device__ float g_qkv[(size_t)MR * 3 * EE];   // 96 MB (fp32, attention input)
__device__ float g_r1 [(size_t)MR * EE];       // 32 MB
__device__ float g_x1 [(size_t)MR * EE];       // 32 MB (fp32 for FFN2 residual)
__device__ float g_r2 [(size_t)MR * EE];       // 32 MB

__device__ bf16 g_x_h  [(size_t)MR * EE];
__device__ bf16 g_x_l  [(size_t)MR * EE];
__device__ bf16 g_att_h[(size_t)MR * EE];
__device__ bf16 g_att_l[(size_t)MR * EE];
__device__ bf16 g_x1_h [(size_t)MR * EE];
__device__ bf16 g_x1_l [(size_t)MR * EE];
__device__ bf16 g_h_h  [(size_t)MR * FFD];
__device__ bf16 g_h_l  [(size_t)MR * FFD];

__device__ bf16 g_wqkv_h[(size_t)3 * EE * EE];
__device__ bf16 g_wqkv_l[(size_t)3 * EE * EE];
__device__ bf16 g_wout_h[(size_t)EE * EE];
__device__ bf16 g_wout_l[(size_t)EE * EE];
__device__ bf16 g_w1_h  [(size_t)FFD * EE];
__device__ bf16 g_w1_l  [(size_t)FFD * EE];
__device__ bf16 g_w2_h  [(size_t)EE * FFD];
__device__ bf16 g_w2_l  [(size_t)EE * FFD];

// ---------------------------------------------------------------------------
// Helpers
// ---------------------------------------------------------------------------
__device__ __forceinline__ uint32_t smem_u32(const void* p) {
    uint32_t a;
    asm("{ .reg .u64 t; cvta.to.shared.u64 t, %1; cvt.u32.u64 %0, t; }"
        : "=r"(a) : "l"(p));
    return a;
}

__device__ __forceinline__ void mma16816(float* c, const uint32_t* a, const uint32_t* b) {
    asm volatile(
        "mma.sync.aligned.m16n8k16.row.col.f32.bf16.bf16.f32 "
        "{%0,%1,%2,%3}, {%4,%5,%6,%7}, {%8,%9}, {%0,%1,%2,%3};"
        : "+f"(c[0]), "+f"(c[1]), "+f"(c[2]), "+f"(c[3])
        : "r"(a[0]), "r"(a[1]), "r"(a[2]), "r"(a[3]), "r"(b[0]), "r"(b[1]));
}

__device__ __forceinline__ void ldsm4(uint32_t* r, uint32_t addr) {
    asm volatile("ldmatrix.sync.aligned.m8n8.x4.shared.b16 {%0,%1,%2,%3}, [%4];"
        : "=r"(r[0]), "=r"(r[1]), "=r"(r[2]), "=r"(r[3]) : "r"(addr));
}

__device__ __forceinline__ void ldsm4t(uint32_t* r, uint32_t addr) {
    asm volatile("ldmatrix.sync.aligned.m8n8.x4.trans.shared.b16 {%0,%1,%2,%3}, [%4];"
        : "=r"(r[0]), "=r"(r[1]), "=r"(r[2]), "=r"(r[3]) : "r"(addr));
}

__device__ __forceinline__ void cp16(uint32_t saddr, const void* g) {
    asm volatile("cp.async.cg.shared.global [%0], [%1], 16;" :: "r"(saddr), "l"(g) : "memory");
}
#define CP_COMMIT() asm volatile("cp.async.commit_group;" ::: "memory")

// split pair of floats into hi/lo bf16x2 words
__device__ __forceinline__ void split2(float a, float b, uint32_t& hh, uint32_t& ll) {
    asm("cvt.rn.bf16x2.f32 %0,%1,%2;" : "=r"(hh) : "f"(b), "f"(a));
    float ra = a - __uint_as_float(hh << 16);
    float rb = b - __uint_as_float(hh & 0xFFFF0000u);
    asm("cvt.rn.bf16x2.f32 %0,%1,%2;" : "=r"(ll) : "f"(rb), "f"(ra));
}

__device__ __forceinline__ void cvt_store8(char* hi, char* lo, uint32_t boff, float4 v) {
    uint32_t h0, h1, l0, l1;
    split2(v.x, v.y, h0, l0);
    split2(v.z, v.w, h1, l1);
    *(uint2*)(hi + boff) = make_uint2(h0, h1);
    *(uint2*)(lo + boff) = make_uint2(l0, l1);
}

// ---------------------------------------------------------------------------
// fp32 -> bf16 hi/lo split kernel
// ---------------------------------------------------------------------------
__global__ __launch_bounds__(256)
void split_kernel(const float* __restrict__ s, bf16* __restrict__ h,
                  bf16* __restrict__ l, int n4)
{
    int i = blockIdx.x * 256 + threadIdx.x;
    if (i >= n4) return;
    float4 v = ((const float4*)s)[i];
    uint32_t h0, h1, l0, l1;
    split2(v.x, v.y, h0, l0);
    split2(v.z, v.w, h1, l1);
    ((uint2*)h)[i] = make_uint2(h0, h1);
    ((uint2*)l)[i] = make_uint2(l0, l1);
}

// ---------------------------------------------------------------------------
// GEMM on pre-split bf16 hi/lo inputs: C = A @ W^T (+bias, +res, relu)
// CTA 128x128, BK=32, 256 thr. 3-stage cp.async pipeline, ONE sync/iter.
// No min-blocks bound (smem 120KB -> occupancy 1; no register cap/spills).
// ---------------------------------------------------------------------------
#define SBYTE 80
#define TO_AH 0
#define TO_AL 10240
#define TO_BH 20480
#define TO_BL 30720
#define STAGE 40960
#define GSM_TOTAL (3 * STAGE)

template<bool RELU, bool RES, bool OUTBF>
__global__ __launch_bounds__(256)
void gemm_bf(const bf16* __restrict__ Ah, const bf16* __restrict__ Al,
             const bf16* __restrict__ Bh, const bf16* __restrict__ Bl,
             const float* __restrict__ bias, const float* __restrict__ res,
             float* __restrict__ C, bf16* __restrict__ Ch, bf16* __restrict__ Cl,
             int N, int K)
{
    extern __shared__ char sm[];
    const int tid = threadIdx.x, lane = tid & 31, wid = tid >> 5;
    const int wm = wid & 1;
    const int wn = wid >> 1;
    const int bm = blockIdx.y * 128, bn = blockIdx.x * 128;
    const uint32_t sbase = smem_u32(sm);

    const uint32_t a_off = (uint32_t)(wm * 64 + (lane & 15)) * SBYTE + ((lane >> 4) * 16);
    const uint32_t b_off = (uint32_t)(wn * 32 + (lane & 7) + ((lane >> 4) << 3)) * SBYTE
                         + (((lane >> 3) & 1) * 16);

    const bf16* Abh = Ah + (size_t)bm * K;
    const bf16* Abl = Al + (size_t)bm * K;
    const bf16* Bbh = Bh + (size_t)bn * K;
    const bf16* Bbl = Bl + (size_t)bn * K;

    auto load_stage = [&](int buf, int kt) {
        const uint32_t s2 = sbase + buf * STAGE;
#pragma unroll
        for (int i = 0; i < 2; i++) {
            int ch  = tid + 256 * i;
            int row = ch >> 2, c = ch & 3;
            uint32_t so = (uint32_t)row * SBYTE + c * 16;
            size_t   go = (size_t)row * K + (size_t)kt * 32 + c * 8;
            cp16(s2 + TO_AH + so, Abh + go);
            cp16(s2 + TO_AL + so, Abl + go);
            cp16(s2 + TO_BH + so, Bbh + go);
            cp16(s2 + TO_BL + so, Bbl + go);
        }
        CP_COMMIT();
    };

    float acc[4][4][4];
#pragma unroll
    for (int mt = 0; mt < 4; mt++)
#pragma unroll
        for (int nt = 0; nt < 4; nt++)
#pragma unroll
            for (int j = 0; j < 4; j++) acc[mt][nt][j] = 0.f;

    load_stage(0, 0);
    load_stage(1, 1);

    const int KT = K >> 5;
    int cur = 0;                       // stage index kt % 3
    for (int kt = 0; kt < KT; kt++) {
        if (kt + 1 < KT) { asm volatile("cp.async.wait_group 1;" ::: "memory"); }
        else             { asm volatile("cp.async.wait_group 0;" ::: "memory"); }
        __syncthreads();

        // issue loads for kt+2 into the free buffer (≠ cur, ≠ cur+1)
        if (kt + 2 < KT) {
            int nb = cur + 2; if (nb >= 3) nb -= 3;
            load_stage(nb, kt + 2);
        }

        const uint32_t base = sbase + cur * STAGE;
#pragma unroll
        for (int ks = 0; ks < 2; ks++) {
            uint32_t ah[4][4], al[4][4], bh[2][4], bl[2][4];
#pragma unroll
            for (int t = 0; t < 4; t++) {
                ldsm4(ah[t], base + TO_AH + a_off + t * (16 * SBYTE) + ks * 32);
                ldsm4(al[t], base + TO_AL + a_off + t * (16 * SBYTE) + ks * 32);
            }
#pragma unroll
            for (int i = 0; i < 2; i++) {
                ldsm4(bh[i], base + TO_BH + b_off + i * (16 * SBYTE) + ks * 32);
                ldsm4(bl[i], base + TO_BL + b_off + i * (16 * SBYTE) + ks * 32);
            }
#pragma unroll
            for (int mt = 0; mt < 4; mt++)
#pragma unroll
                for (int nt = 0; nt < 4; nt++) {
                    const uint32_t* bph = &bh[nt >> 1][(nt & 1) * 2];
                    const uint32_t* bpl = &bl[nt >> 1][(nt & 1) * 2];
                    mma16816(acc[mt][nt], al[mt], bph);
                    mma16816(acc[mt][nt], ah[mt], bpl);
                    mma16816(acc[mt][nt], ah[mt], bph);
                }
        }
        if (++cur == 3) cur = 0;
    }

    // Epilogue
    const int erow = bm + wm * 64 + (lane >> 2);
    const int ecol = bn + wn * 32 + (lane & 3) * 2;
#pragma unroll
    for (int mt = 0; mt < 4; mt++)
#pragma unroll
        for (int nt = 0; nt < 4; nt++) {
            const int col = ecol + nt * 8;
            float2 bv = *(const float2*)(bias + col);
#pragma unroll
            for (int h2 = 0; h2 < 2; h2++) {
                const int row = erow + mt * 16 + h2 * 8;
                float o0 = acc[mt][nt][h2 * 2 + 0] + bv.x;
                float o1 = acc[mt][nt][h2 * 2 + 1] + bv.y;
                if (RES) {
                    float2 rv = *(const float2*)(res + (size_t)row * N + col);
                    o0 += rv.x; o1 += rv.y;
                }
                if (RELU) { o0 = fmaxf(o0, 0.f); o1 = fmaxf(o1, 0.f); }
                if (OUTBF) {
                    uint32_t hh, ll;
                    split2(o0, o1, hh, ll);
                    *(uint32_t*)(Ch + (size_t)row * N + col) = hh;
                    *(uint32_t*)(Cl + (size_t)row * N + col) = ll;
                } else {
                    *(float2*)(C + (size_t)row * N + col) = make_float2(o0, o1);
                }
            }
        }
}

// ---------------------------------------------------------------------------
// Flash attention via mma.sync (bf16 3-pass split) — epilogue emits bf16 hi/lo
// ---------------------------------------------------------------------------
#define ASTR   144
#define AQ_HI  0
#define AQ_LO  (128 * ASTR)
#define AK_HI  (2 * 128 * ASTR)
#define AK_LO  (AK_HI + 64 * ASTR)
#define AV_HI  (AK_LO + 64 * ASTR)
#define AV_LO  (AV_HI + 64 * ASTR)
#define ATT_SMEM (AV_LO + 64 * ASTR)   /* 73728 */

__global__ __launch_bounds__(256, 1)
void attn_mma(const float* __restrict__ qkv,
              bf16* __restrict__ out_h, bf16* __restrict__ out_l)
{
    extern __shared__ char sm[];
    const uint32_t sb = smem_u32(sm);
    const int tid = threadIdx.x, lane = tid & 31, w = tid >> 5;
    const int qt = blockIdx.x;
    const int bh = blockIdx.y;
    const int b = bh >> 4, h = bh & 15;

    const float* base = qkv + (size_t)b * SS * (3 * EE);

    {
        const int c4q = tid & 15, r0q = tid >> 4;
#pragma unroll
        for (int i = 0; i < 8; i++) {
            int r = r0q + 16 * i;
            float4 v = *(const float4*)(base + (size_t)(qt * 128 + r) * (3 * EE) + h * 64 + c4q * 4);
            v.x *= 0.125f; v.y *= 0.125f; v.z *= 0.125f; v.w *= 0.125f;
            cvt_store8(sm + AQ_HI, sm + AQ_LO, (uint32_t)r * ASTR + c4q * 8, v);
        }
    }

    const int c4 = tid & 15, kr0 = tid >> 4;
    const float* kbase = qkv + (size_t)b * SS * (3 * EE) + EE + h * 64 + c4 * 4;
    const float* vbase = kbase + EE;

    float4 kreg[4], vreg[4];
#pragma unroll
    for (int i = 0; i < 4; i++) {
        kreg[i] = *(const float4*)(kbase + (size_t)(kr0 + 16 * i) * (3 * EE));
        vreg[i] = *(const float4*)(vbase + (size_t)(kr0 + 16 * i) * (3 * EE));
    }
#pragma unroll
    for (int i = 0; i < 4; i++) {
        uint32_t o = (uint32_t)(kr0 + 16 * i) * ASTR + c4 * 8;
        cvt_store8(sm + AK_HI, sm + AK_LO, o, kreg[i]);
        cvt_store8(sm + AV_HI, sm + AV_LO, o, vreg[i]);
    }
    __syncthreads();

    const uint32_t a_off = (uint32_t)(w * 16 + (lane & 15)) * ASTR + ((lane >> 4) * 16);
    const uint32_t b_off = (uint32_t)((lane & 7) + ((lane >> 4) << 3)) * ASTR
                         + (((lane >> 3) & 1) * 16);
    const uint32_t v_off = (uint32_t)(lane & 15) * ASTR + ((lane >> 4) * 16);

    float mA = -1e30f, mB = -1e30f, lA = 0.f, lB = 0.f;
    float O[8][4];
#pragma unroll
    for (int j = 0; j < 8; j++)
#pragma unroll
        for (int k = 0; k < 4; k++) O[j][k] = 0.f;

    const int NT = SS / 64;
    for (int kt = 0; kt < NT; kt++) {
        const bool more = (kt + 1 < NT);
        if (more) {
#pragma unroll
            for (int i = 0; i < 4; i++) {
                kreg[i] = *(const float4*)(kbase + (size_t)((kt + 1) * 64 + kr0 + 16 * i) * (3 * EE));
                vreg[i] = *(const float4*)(vbase + (size_t)((kt + 1) * 64 + kr0 + 16 * i) * (3 * EE));
            }
        }

        float S[8][4];
#pragma unroll
        for (int j = 0; j < 8; j++)
#pragma unroll
            for (int k = 0; k < 4; k++) S[j][k] = 0.f;

#pragma unroll
        for (int kd = 0; kd < 4; kd++) {
            uint32_t ah[4], al[4];
            ldsm4(ah, sb + AQ_HI + a_off + kd * 32);
            ldsm4(al, sb + AQ_LO + a_off + kd * 32);
#pragma unroll
            for (int i = 0; i < 4; i++) {
                uint32_t bh4[4], bl4[4];
                ldsm4(bh4, sb + AK_HI + b_off + i * (16 * ASTR) + kd * 32);
                ldsm4(bl4, sb + AK_LO + b_off + i * (16 * ASTR) + kd * 32);
                mma16816(S[2 * i],     al, &bh4[0]);
                mma16816(S[2 * i],     ah, &bl4[0]);
                mma16816(S[2 * i],     ah, &bh4[0]);
                mma16816(S[2 * i + 1], al, &bh4[2]);
                mma16816(S[2 * i + 1], ah, &bl4[2]);
                mma16816(S[2 * i + 1], ah, &bh4[2]);
            }
        }

        float txA = -1e30f, txB = -1e30f;
#pragma unroll
        for (int j = 0; j < 8; j++) {
            txA = fmaxf(txA, fmaxf(S[j][0], S[j][1]));
            txB = fmaxf(txB, fmaxf(S[j][2], S[j][3]));
        }
        txA = fmaxf(txA, __shfl_xor_sync(0xffffffffu, txA, 1));
        txA = fmaxf(txA, __shfl_xor_sync(0xffffffffu, txA, 2));
        txB = fmaxf(txB, __shfl_xor_sync(0xffffffffu, txB, 1));
        txB = fmaxf(txB, __shfl_xor_sync(0xffffffffu, txB, 2));
        const float mnA = fmaxf(mA, txA), mnB = fmaxf(mB, txB);
        const float cA = __expf(mA - mnA), cB = __expf(mB - mnB);

        float sA = 0.f, sB = 0.f;
#pragma unroll
        for (int j = 0; j < 8; j++) {
            S[j][0] = __expf(S[j][0] - mnA);
            S[j][1] = __expf(S[j][1] - mnA);
            S[j][2] = __expf(S[j][2] - mnB);
            S[j][3] = __expf(S[j][3] - mnB);
            sA += S[j][0] + S[j][1];
            sB += S[j][2] + S[j][3];
        }
        sA += __shfl_xor_sync(0xffffffffu, sA, 1);
        sA += __shfl_xor_sync(0xffffffffu, sA, 2);
        sB += __shfl_xor_sync(0xffffffffu, sB, 1);
        sB += __shfl_xor_sync(0xffffffffu, sB, 2);
        lA = lA * cA + sA;  mA = mnA;
        lB = lB * cB + sB;  mB = mnB;
#pragma unroll
        for (int j = 0; j < 8; j++) {
            O[j][0] *= cA; O[j][1] *= cA;
            O[j][2] *= cB; O[j][3] *= cB;
        }

#pragma unroll
        for (int kk = 0; kk < 4; kk++) {
            uint32_t ph[4], pl[4];
#pragma unroll
            for (int u = 0; u < 2; u++) {
                const float* sp = S[2 * kk + u];
#pragma unroll
                for (int hf = 0; hf < 2; hf++) {
                    uint32_t hh, ll;
                    split2(sp[2 * hf], sp[2 * hf + 1], hh, ll);
                    ph[2 * u + hf] = hh;
                    pl[2 * u + hf] = ll;
                }
            }
#pragma unroll
            for (int dimc = 0; dimc < 4; dimc++) {
                uint32_t vh[4], vl[4];
                ldsm4t(vh, sb + AV_HI + v_off + (uint32_t)(kk * 16) * ASTR + dimc * 32);
                ldsm4t(vl, sb + AV_LO + v_off + (uint32_t)(kk * 16) * ASTR + dimc * 32);
                mma16816(O[2 * dimc],     pl, &vh[0]);
                mma16816(O[2 * dimc],     ph, &vl[0]);
                mma16816(O[2 * dimc],     ph, &vh[0]);
                mma16816(O[2 * dimc + 1], pl, &vh[2]);
                mma16816(O[2 * dimc + 1], ph, &vl[2]);
                mma16816(O[2 * dimc + 1], ph, &vh[2]);
            }
        }

        __syncthreads();
        if (more) {
#pragma unroll
            for (int i = 0; i < 4; i++) {
                uint32_t o = (uint32_t)(kr0 + 16 * i) * ASTR + c4 * 8;
                cvt_store8(sm + AK_HI, sm + AK_LO, o, kreg[i]);
                cvt_store8(sm + AV_HI, sm + AV_LO, o, vreg[i]);
            }
            __syncthreads();
        }
    }

    // epilogue -> bf16 hi/lo
    const float invA = 1.f / lA, invB = 1.f / lB;
    const size_t rowA = (size_t)b * SS + qt * 128 + w * 16 + (lane >> 2);
    const size_t idxA = rowA * EE + h * 64 + (lane & 3) * 2;
#pragma unroll
    for (int j = 0; j < 8; j++) {
        uint32_t hh, ll;
        split2(O[j][0] * invA, O[j][1] * invA, hh, ll);
        *(uint32_t*)(out_h + idxA + j * 8) = hh;
        *(uint32_t*)(out_l + idxA + j * 8) = ll;
        split2(O[j][2] * invB, O[j][3] * invB, hh, ll);
        *(uint32_t*)(out_h + idxA + (size_t)8 * EE + j * 8) = hh;
        *(uint32_t*)(out_l + idxA + (size_t)8 * EE + j * 8) = ll;
    }
}

// ---------------------------------------------------------------------------
// LayerNorm — optionally emits bf16 hi/lo alongside fp32
// ---------------------------------------------------------------------------
template<bool EMIT>
__global__ __launch_bounds__(256)
void ln_kernel(const float* __restrict__ r, const float* __restrict__ g,
               const float* __restrict__ be, float* __restrict__ out,
               bf16* __restrict__ oh, bf16* __restrict__ ol)
{
    const int row = blockIdx.x;
    const int tid = threadIdx.x;
    const int lane = tid & 31, warp = tid >> 5;

    float4 v = ((const float4*)(r + (size_t)row * EE))[tid];
    float s  = v.x + v.y + v.z + v.w;
    float sq = v.x * v.x + v.y * v.y + v.z * v.z + v.w * v.w;
#pragma unroll
    for (int o = 16; o; o >>= 1) {
        s  += __shfl_xor_sync(0xffffffffu, s,  o);
        sq += __shfl_xor_sync(0xffffffffu, sq, o);
    }
    __shared__ float ss[8], ssq[8];
    if (lane == 0) { ss[warp] = s; ssq[warp] = sq; }
    __syncthreads();
    float ts = 0.f, tq = 0.f;
#pragma unroll
    for (int i = 0; i < 8; i++) { ts += ss[i]; tq += ssq[i]; }
    float mu   = ts * (1.0f / EE);
    float var  = tq * (1.0f / EE) - mu * mu;
    float rstd = rsqrtf(var + 1e-5f);

    float4 gv = ((const float4*)g)[tid];
    float4 bv = ((const float4*)be)[tid];
    float4 o;
    o.x = (v.x - mu) * rstd * gv.x + bv.x;
    o.y = (v.y - mu) * rstd * gv.y + bv.y;
    o.z = (v.z - mu) * rstd * gv.z + bv.z;
    o.w = (v.w - mu) * rstd * gv.w + bv.w;
    ((float4*)(out + (size_t)row * EE))[tid] = o;
    if (EMIT) {
        uint32_t h0, h1, l0, l1;
        split2(o.x, o.y, h0, l0);
        split2(o.z, o.w, h1, l1);
        ((uint2*)(oh + (size_t)row * EE))[tid] = make_uint2(h0, h1);
        ((uint2*)(ol + (size_t)row * EE))[tid] = make_uint2(l0, l1);
    }
}

// ---------------------------------------------------------------------------
// Launch
// ---------------------------------------------------------------------------
extern "C" void kernel_launch(void* const* d_in, const int* in_sizes, int n_in,
                              void* d_out, int out_size)
{
    (void)in_sizes; (void)n_in; (void)out_size;
    const float* x     = (const float*)d_in[0];
    const float* w_qkv = (const float*)d_in[1];
    const float* b_qkv = (const float*)d_in[2];
    const float* w_out = (const float*)d_in[3];
    const float* b_out = (const float*)d_in[4];
    const float* w1    = (const float*)d_in[5];
    const float* b1    = (const float*)d_in[6];
    const float* w2    = (const float*)d_in[7];
    const float* b2    = (const float*)d_in[8];
    const float* g1    = (const float*)d_in[9];
    const float* be1   = (const float*)d_in[10];
    const float* g2    = (const float*)d_in[11];
    const float* be2   = (const float*)d_in[12];
    float* out = (float*)d_out;

    float *p_qkv, *p_r1, *p_x1, *p_r2;
    bf16 *p_xh, *p_xl, *p_ath, *p_atl, *p_x1h, *p_x1l, *p_hh, *p_hl;
    bf16 *p_wqh, *p_wql, *p_woh, *p_wol, *p_w1h, *p_w1l, *p_w2h, *p_w2l;
    cudaGetSymbolAddress((void**)&p_qkv, g_qkv);
    cudaGetSymbolAddress((void**)&p_r1,  g_r1);
    cudaGetSymbolAddress((void**)&p_x1,  g_x1);
    cudaGetSymbolAddress((void**)&p_r2,  g_r2);
    cudaGetSymbolAddress((void**)&p_xh,  g_x_h);
    cudaGetSymbolAddress((void**)&p_xl,  g_x_l);
    cudaGetSymbolAddress((void**)&p_ath, g_att_h);
    cudaGetSymbolAddress((void**)&p_atl, g_att_l);
    cudaGetSymbolAddress((void**)&p_x1h, g_x1_h);
    cudaGetSymbolAddress((void**)&p_x1l, g_x1_l);
    cudaGetSymbolAddress((void**)&p_hh,  g_h_h);
    cudaGetSymbolAddress((void**)&p_hl,  g_h_l);
    cudaGetSymbolAddress((void**)&p_wqh, g_wqkv_h);
    cudaGetSymbolAddress((void**)&p_wql, g_wqkv_l);
    cudaGetSymbolAddress((void**)&p_woh, g_wout_h);
    cudaGetSymbolAddress((void**)&p_wol, g_wout_l);
    cudaGetSymbolAddress((void**)&p_w1h, g_w1_h);
    cudaGetSymbolAddress((void**)&p_w1l, g_w1_l);
    cudaGetSymbolAddress((void**)&p_w2h, g_w2_h);
    cudaGetSymbolAddress((void**)&p_w2l, g_w2_l);

    cudaFuncSetAttribute(attn_mma, cudaFuncAttributeMaxDynamicSharedMemorySize, ATT_SMEM);
    cudaFuncSetAttribute(gemm_bf<false, false, false>, cudaFuncAttributeMaxDynamicSharedMemorySize, GSM_TOTAL);
    cudaFuncSetAttribute(gemm_bf<false, true,  false>, cudaFuncAttributeMaxDynamicSharedMemorySize, GSM_TOTAL);
    cudaFuncSetAttribute(gemm_bf<true,  false, true>,  cudaFuncAttributeMaxDynamicSharedMemorySize, GSM_TOTAL);

    // 0) split inputs/weights to bf16 hi/lo
    split_kernel<<<(MR * EE / 4) / 256, 256>>>(x, p_xh, p_xl, MR * EE / 4);
    split_kernel<<<(3 * EE * EE / 4) / 256, 256>>>(w_qkv, p_wqh, p_wql, 3 * EE * EE / 4);
    split_kernel<<<(EE * EE / 4) / 256, 256>>>(w_out, p_woh, p_wol, EE * EE / 4);
    split_kernel<<<(FFD * EE / 4) / 256, 256>>>(w1, p_w1h, p_w1l, FFD * EE / 4);
    split_kernel<<<(EE * FFD / 4) / 256, 256>>>(w2, p_w2h, p_w2l, EE * FFD / 4);

    // 1) QKV projection -> fp32 qkv
    gemm_bf<false, false, false><<<dim3(3 * EE / 128, MR / 128), 256, GSM_TOTAL>>>(
        p_xh, p_xl, p_wqh, p_wql, b_qkv, nullptr, p_qkv, nullptr, nullptr, 3 * EE, EE);

    // 2) attention -> bf16 hi/lo
    attn_mma<<<dim3(SS / 128, BB * HHN), 256, ATT_SMEM>>>(p_qkv, p_ath, p_atl);

    // 3) out-proj + residual(x) -> r1 fp32
    gemm_bf<false, true, false><<<dim3(EE / 128, MR / 128), 256, GSM_TOTAL>>>(
        p_ath, p_atl, p_woh, p_wol, b_out, x, p_r1, nullptr, nullptr, EE, EE);

    // 4) LN1 -> x1 fp32 + bf16 hi/lo
    ln_kernel<true><<<MR, 256>>>(p_r1, g1, be1, p_x1, p_x1h, p_x1l);

    // 5) FFN up + ReLU -> h bf16 hi/lo
    gemm_bf<true, false, true><<<dim3(FFD / 128, MR / 128), 256, GSM_TOTAL>>>(
        p_x1h, p_x1l, p_w1h, p_w1l, b1, nullptr, nullptr, p_hh, p_hl, FFD, EE);

    // 6) FFN down + residual(x1) -> r2 fp32
    gemm_bf<false, true, false><<<dim3(EE / 128, MR / 128), 256, GSM_TOTAL>>>(
        p_hh, p_hl, p_w2h, p_w2l, b2, p_x1, p_r2, nullptr, nullptr, EE, FFD);

    // 7) LN2 -> out
    ln_kernel<false><<<MR, 256>>>(p_r2, g2, be2, out, nullptr, nullptr);
}

// round 9
// speedup vs baseline: 1.1208x; 1.1208x over previous
#include <cuda_runtime.h>
#include <cuda_bf16.h>
#include <cstdint>
#include <math.h>

// Problem constants
#define BB   4
#define SS   2048
#define EE   1024
#define HHN  16
#define DKH  64
#define FFD  4096
#define MR   (BB*SS)   /* 8192 rows */

typedef __nv_bfloat16 bf16;

// ---------------------------------------------------------------------------
// Scratch
// ---------------------------------------------------------------------------
__device__ float g_qkv[(size_t)MR * 3 * EE];   // 96 MB
__device__ float g_att[(size_t)MR * EE];       // 32 MB
__device__ float g_r1 [(size_t)MR * EE];       // 32 MB
__device__ float g_x1 [(size_t)MR * EE];       // 32 MB
__device__ float g_h  [(size_t)MR * FFD];      // 128 MB
__device__ float g_r2 [(size_t)MR * EE];       // 32 MB

// pre-split weights (bf16 hi/lo)
__device__ bf16 g_wqkv_h[(size_t)3 * EE * EE];
__device__ bf16 g_wqkv_l[(size_t)3 * EE * EE];
__device__ bf16 g_wout_h[(size_t)EE * EE];
__device__ bf16 g_wout_l[(size_t)EE * EE];
__device__ bf16 g_w1_h  [(size_t)FFD * EE];
__device__ bf16 g_w1_l  [(size_t)FFD * EE];
__device__ bf16 g_w2_h  [(size_t)EE * FFD];
__device__ bf16 g_w2_l  [(size_t)EE * FFD];

// ---------------------------------------------------------------------------
// Helpers
// ---------------------------------------------------------------------------
__device__ __forceinline__ uint32_t smem_u32(const void* p) {
    uint32_t a;
    asm("{ .reg .u64 t; cvta.to.shared.u64 t, %1; cvt.u32.u64 %0, t; }"
        : "=r"(a) : "l"(p));
    return a;
}

__device__ __forceinline__ void mma16816(float* c, const uint32_t* a, const uint32_t* b) {
    asm volatile(
        "mma.sync.aligned.m16n8k16.row.col.f32.bf16.bf16.f32 "
        "{%0,%1,%2,%3}, {%4,%5,%6,%7}, {%8,%9}, {%0,%1,%2,%3};"
        : "+f"(c[0]), "+f"(c[1]), "+f"(c[2]), "+f"(c[3])
        : "r"(a[0]), "r"(a[1]), "r"(a[2]), "r"(a[3]), "r"(b[0]), "r"(b[1]));
}

__device__ __forceinline__ void ldsm4(uint32_t* r, uint32_t addr) {
    asm volatile("ldmatrix.sync.aligned.m8n8.x4.shared.b16 {%0,%1,%2,%3}, [%4];"
        : "=r"(r[0]), "=r"(r[1]), "=r"(r[2]), "=r"(r[3]) : "r"(addr));
}

__device__ __forceinline__ void ldsm4t(uint32_t* r, uint32_t addr) {
    asm volatile("ldmatrix.sync.aligned.m8n8.x4.trans.shared.b16 {%0,%1,%2,%3}, [%4];"
        : "=r"(r[0]), "=r"(r[1]), "=r"(r[2]), "=r"(r[3]) : "r"(addr));
}

__device__ __forceinline__ void split2(float a, float b, uint32_t& hh, uint32_t& ll) {
    asm("cvt.rn.bf16x2.f32 %0,%1,%2;" : "=r"(hh) : "f"(b), "f"(a));
    float ra = a - __uint_as_float(hh << 16);
    float rb = b - __uint_as_float(hh & 0xFFFF0000u);
    asm("cvt.rn.bf16x2.f32 %0,%1,%2;" : "=r"(ll) : "f"(rb), "f"(ra));
}

__device__ __forceinline__ void cvt_store8(char* hi, char* lo, uint32_t boff, float4 v) {
    uint32_t h0, h1, l0, l1;
    split2(v.x, v.y, h0, l0);
    split2(v.z, v.w, h1, l1);
    *(uint2*)(hi + boff) = make_uint2(h0, h1);
    *(uint2*)(lo + boff) = make_uint2(l0, l1);
}

// ---------------------------------------------------------------------------
// fp32 -> bf16 hi/lo split kernel (weights only)
// ---------------------------------------------------------------------------
__global__ __launch_bounds__(256)
void split_kernel(const float* __restrict__ s, bf16* __restrict__ h,
                  bf16* __restrict__ l, int n4)
{
    int i = blockIdx.x * 256 + threadIdx.x;
    if (i >= n4) return;
    float4 v = ((const float4*)s)[i];
    uint32_t h0, h1, l0, l1;
    split2(v.x, v.y, h0, l0);
    split2(v.z, v.w, h1, l1);
    ((uint2*)h)[i] = make_uint2(h0, h1);
    ((uint2*)l)[i] = make_uint2(l0, l1);
}

// ---------------------------------------------------------------------------
// Hybrid GEMM: A fp32 (split in-kernel), W pre-split bf16 hi/lo.
// C[M,N] = A[M,K] @ W[N,K]^T (+bias, +res, relu).
// CTA 128x128, BK=32, 256 thr (2M x 4N warps), double-buffered (R5 structure).
// ---------------------------------------------------------------------------
#define SBYTE 80
#define TILE_A_HI 0
#define TILE_A_LO 10240
#define TILE_B_HI 20480
#define TILE_B_LO 30720
#define STAGE     40960
#define GSM_TOTAL (2 * STAGE)

template<bool RELU, bool RES>
__global__ __launch_bounds__(256, 1)
void gemm_hy(const float* __restrict__ A,
             const bf16* __restrict__ Bh, const bf16* __restrict__ Bl,
             const float* __restrict__ bias, const float* __restrict__ res,
             float* __restrict__ C, int N, int K)
{
    extern __shared__ char sm[];
    const int tid = threadIdx.x, lane = tid & 31, wid = tid >> 5;
    const int wm = wid & 1;
    const int wn = wid >> 1;
    const int bm = blockIdx.y * 128, bn = blockIdx.x * 128;
    const uint32_t sbase = smem_u32(sm);

    const uint32_t a_off = (uint32_t)(wm * 64 + (lane & 15)) * SBYTE + ((lane >> 4) * 16);
    const uint32_t b_off = (uint32_t)(wn * 32 + (lane & 7) + ((lane >> 4) << 3)) * SBYTE
                         + (((lane >> 3) & 1) * 16);

    // A loader mapping: rows arow+32i, float4 col ac4
    const int ac4 = tid & 7, arow = tid >> 3;
    const float* Ap = A + (size_t)(bm + arow) * K + ac4 * 4;
    const uint32_t a_st = (uint32_t)arow * SBYTE + ac4 * 8;

    // B loader mapping: rows brow+64i, 16B chunk bc
    const int bc = tid & 3, brow = tid >> 2;
    const bf16* Bph = Bh + (size_t)(bn + brow) * K + bc * 8;
    const bf16* Bpl = Bl + (size_t)(bn + brow) * K + bc * 8;
    const uint32_t b_st = (uint32_t)brow * SBYTE + bc * 16;

    float acc[4][4][4];
#pragma unroll
    for (int mt = 0; mt < 4; mt++)
#pragma unroll
        for (int nt = 0; nt < 4; nt++)
#pragma unroll
            for (int j = 0; j < 4; j++) acc[mt][nt][j] = 0.f;

    float4 va[4];
    uint4  vbh[2], vbl[2];
#pragma unroll
    for (int i = 0; i < 4; i++)
        va[i] = *(const float4*)(Ap + (size_t)(32 * i) * K);
#pragma unroll
    for (int i = 0; i < 2; i++) {
        vbh[i] = *(const uint4*)(Bph + (size_t)(64 * i) * K);
        vbl[i] = *(const uint4*)(Bpl + (size_t)(64 * i) * K);
    }
#pragma unroll
    for (int i = 0; i < 4; i++)
        cvt_store8(sm + TILE_A_HI, sm + TILE_A_LO, a_st + i * 32 * SBYTE, va[i]);
#pragma unroll
    for (int i = 0; i < 2; i++) {
        *(uint4*)(sm + TILE_B_HI + b_st + i * 64 * SBYTE) = vbh[i];
        *(uint4*)(sm + TILE_B_LO + b_st + i * 64 * SBYTE) = vbl[i];
    }
    __syncthreads();

    const int KT = K >> 5;
    for (int kt = 0; kt < KT; kt++) {
        if (kt + 1 < KT) {
#pragma unroll
            for (int i = 0; i < 4; i++)
                va[i] = *(const float4*)(Ap + (size_t)(32 * i) * K + (kt + 1) * 32);
#pragma unroll
            for (int i = 0; i < 2; i++) {
                vbh[i] = *(const uint4*)(Bph + (size_t)(64 * i) * K + (kt + 1) * 32);
                vbl[i] = *(const uint4*)(Bpl + (size_t)(64 * i) * K + (kt + 1) * 32);
            }
        }
        const uint32_t base = sbase + (kt & 1) * STAGE;
#pragma unroll
        for (int ks = 0; ks < 2; ks++) {
            uint32_t ah[4][4], al[4][4], bh[2][4], bl[2][4];
#pragma unroll
            for (int t = 0; t < 4; t++) {
                ldsm4(ah[t], base + TILE_A_HI + a_off + t * (16 * SBYTE) + ks * 32);
                ldsm4(al[t], base + TILE_A_LO + a_off + t * (16 * SBYTE) + ks * 32);
            }
#pragma unroll
            for (int i = 0; i < 2; i++) {
                ldsm4(bh[i], base + TILE_B_HI + b_off + i * (16 * SBYTE) + ks * 32);
                ldsm4(bl[i], base + TILE_B_LO + b_off + i * (16 * SBYTE) + ks * 32);
            }
#pragma unroll
            for (int mt = 0; mt < 4; mt++)
#pragma unroll
                for (int nt = 0; nt < 4; nt++) {
                    const uint32_t* bph = &bh[nt >> 1][(nt & 1) * 2];
                    const uint32_t* bpl = &bl[nt >> 1][(nt & 1) * 2];
                    mma16816(acc[mt][nt], al[mt], bph);
                    mma16816(acc[mt][nt], ah[mt], bpl);
                    mma16816(acc[mt][nt], ah[mt], bph);
                }
        }
        if (kt + 1 < KT) {
            char* nb = sm + ((kt + 1) & 1) * STAGE;
#pragma unroll
            for (int i = 0; i < 4; i++)
                cvt_store8(nb + TILE_A_HI, nb + TILE_A_LO, a_st + i * 32 * SBYTE, va[i]);
#pragma unroll
            for (int i = 0; i < 2; i++) {
                *(uint4*)(nb + TILE_B_HI + b_st + i * 64 * SBYTE) = vbh[i];
                *(uint4*)(nb + TILE_B_LO + b_st + i * 64 * SBYTE) = vbl[i];
            }
        }
        __syncthreads();
    }

    // Epilogue (R5-identical)
    const int erow = bm + wm * 64 + (lane >> 2);
    const int ecol = bn + wn * 32 + (lane & 3) * 2;
#pragma unroll
    for (int mt = 0; mt < 4; mt++)
#pragma unroll
        for (int nt = 0; nt < 4; nt++) {
            const int col = ecol + nt * 8;
            float2 bv = *(const float2*)(bias + col);
#pragma unroll
            for (int h2 = 0; h2 < 2; h2++) {
                const int row = erow + mt * 16 + h2 * 8;
                float o0 = acc[mt][nt][h2 * 2 + 0] + bv.x;
                float o1 = acc[mt][nt][h2 * 2 + 1] + bv.y;
                if (RES) {
                    float2 rv = *(const float2*)(res + (size_t)row * N + col);
                    o0 += rv.x; o1 += rv.y;
                }
                if (RELU) { o0 = fmaxf(o0, 0.f); o1 = fmaxf(o1, 0.f); }
                *(float2*)(C + (size_t)row * N + col) = make_float2(o0, o1);
            }
        }
}

// ---------------------------------------------------------------------------
// Flash attention via mma.sync (R5-identical, fp32 out)
// ---------------------------------------------------------------------------
#define ASTR   144
#define AQ_HI  0
#define AQ_LO  (128 * ASTR)
#define AK_HI  (2 * 128 * ASTR)
#define AK_LO  (AK_HI + 64 * ASTR)
#define AV_HI  (AK_LO + 64 * ASTR)
#define AV_LO  (AV_HI + 64 * ASTR)
#define ATT_SMEM (AV_LO + 64 * ASTR)   /* 73728 */

__global__ __launch_bounds__(256, 1)
void attn_mma(const float* __restrict__ qkv, float* __restrict__ out)
{
    extern __shared__ char sm[];
    const uint32_t sb = smem_u32(sm);
    const int tid = threadIdx.x, lane = tid & 31, w = tid >> 5;
    const int qt = blockIdx.x;
    const int bh = blockIdx.y;
    const int b = bh >> 4, h = bh & 15;

    const float* base = qkv + (size_t)b * SS * (3 * EE);

    {
        const int c4q = tid & 15, r0q = tid >> 4;
#pragma unroll
        for (int i = 0; i < 8; i++) {
            int r = r0q + 16 * i;
            float4 v = *(const float4*)(base + (size_t)(qt * 128 + r) * (3 * EE) + h * 64 + c4q * 4);
            v.x *= 0.125f; v.y *= 0.125f; v.z *= 0.125f; v.w *= 0.125f;
            cvt_store8(sm + AQ_HI, sm + AQ_LO, (uint32_t)r * ASTR + c4q * 8, v);
        }
    }

    const int c4 = tid & 15, kr0 = tid >> 4;
    const float* kbase = base + EE + h * 64 + c4 * 4;
    const float* vbase = kbase + EE;

    float4 kreg[4], vreg[4];
#pragma unroll
    for (int i = 0; i < 4; i++) {
        kreg[i] = *(const float4*)(kbase + (size_t)(kr0 + 16 * i) * (3 * EE));
        vreg[i] = *(const float4*)(vbase + (size_t)(kr0 + 16 * i) * (3 * EE));
    }
#pragma unroll
    for (int i = 0; i < 4; i++) {
        uint32_t o = (uint32_t)(kr0 + 16 * i) * ASTR + c4 * 8;
        cvt_store8(sm + AK_HI, sm + AK_LO, o, kreg[i]);
        cvt_store8(sm + AV_HI, sm + AV_LO, o, vreg[i]);
    }
    __syncthreads();

    const uint32_t a_off = (uint32_t)(w * 16 + (lane & 15)) * ASTR + ((lane >> 4) * 16);
    const uint32_t b_off = (uint32_t)((lane & 7) + ((lane >> 4) << 3)) * ASTR
                         + (((lane >> 3) & 1) * 16);
    const uint32_t v_off = (uint32_t)(lane & 15) * ASTR + ((lane >> 4) * 16);

    float mA = -1e30f, mB = -1e30f, lA = 0.f, lB = 0.f;
    float O[8][4];
#pragma unroll
    for (int j = 0; j < 8; j++)
#pragma unroll
        for (int k = 0; k < 4; k++) O[j][k] = 0.f;

    const int NT = SS / 64;
    for (int kt = 0; kt < NT; kt++) {
        const bool more = (kt + 1 < NT);
        if (more) {
#pragma unroll
            for (int i = 0; i < 4; i++) {
                kreg[i] = *(const float4*)(kbase + (size_t)((kt + 1) * 64 + kr0 + 16 * i) * (3 * EE));
                vreg[i] = *(const float4*)(vbase + (size_t)((kt + 1) * 64 + kr0 + 16 * i) * (3 * EE));
            }
        }

        float S[8][4];
#pragma unroll
        for (int j = 0; j < 8; j++)
#pragma unroll
            for (int k = 0; k < 4; k++) S[j][k] = 0.f;

#pragma unroll
        for (int kd = 0; kd < 4; kd++) {
            uint32_t ah[4], al[4];
            ldsm4(ah, sb + AQ_HI + a_off + kd * 32);
            ldsm4(al, sb + AQ_LO + a_off + kd * 32);
#pragma unroll
            for (int i = 0; i < 4; i++) {
                uint32_t bh4[4], bl4[4];
                ldsm4(bh4, sb + AK_HI + b_off + i * (16 * ASTR) + kd * 32);
                ldsm4(bl4, sb + AK_LO + b_off + i * (16 * ASTR) + kd * 32);
                mma16816(S[2 * i],     al, &bh4[0]);
                mma16816(S[2 * i],     ah, &bl4[0]);
                mma16816(S[2 * i],     ah, &bh4[0]);
                mma16816(S[2 * i + 1], al, &bh4[2]);
                mma16816(S[2 * i + 1], ah, &bl4[2]);
                mma16816(S[2 * i + 1], ah, &bh4[2]);
            }
        }

        float txA = -1e30f, txB = -1e30f;
#pragma unroll
        for (int j = 0; j < 8; j++) {
            txA = fmaxf(txA, fmaxf(S[j][0], S[j][1]));
            txB = fmaxf(txB, fmaxf(S[j][2], S[j][3]));
        }
        txA = fmaxf(txA, __shfl_xor_sync(0xffffffffu, txA, 1));
        txA = fmaxf(txA, __shfl_xor_sync(0xffffffffu, txA, 2));
        txB = fmaxf(txB, __shfl_xor_sync(0xffffffffu, txB, 1));
        txB = fmaxf(txB, __shfl_xor_sync(0xffffffffu, txB, 2));
        const float mnA = fmaxf(mA, txA), mnB = fmaxf(mB, txB);
        const float cA = __expf(mA - mnA), cB = __expf(mB - mnB);

        float sA = 0.f, sB = 0.f;
#pragma unroll
        for (int j = 0; j < 8; j++) {
            S[j][0] = __expf(S[j][0] - mnA);
            S[j][1] = __expf(S[j][1] - mnA);
            S[j][2] = __expf(S[j][2] - mnB);
            S[j][3] = __expf(S[j][3] - mnB);
            sA += S[j][0] + S[j][1];
            sB += S[j][2] + S[j][3];
        }
        sA += __shfl_xor_sync(0xffffffffu, sA, 1);
        sA += __shfl_xor_sync(0xffffffffu, sA, 2);
        sB += __shfl_xor_sync(0xffffffffu, sB, 1);
        sB += __shfl_xor_sync(0xffffffffu, sB, 2);
        lA = lA * cA + sA;  mA = mnA;
        lB = lB * cB + sB;  mB = mnB;
#pragma unroll
        for (int j = 0; j < 8; j++) {
            O[j][0] *= cA; O[j][1] *= cA;
            O[j][2] *= cB; O[j][3] *= cB;
        }

#pragma unroll
        for (int kk = 0; kk < 4; kk++) {
            uint32_t ph[4], pl[4];
#pragma unroll
            for (int u = 0; u < 2; u++) {
                const float* sp = S[2 * kk + u];
#pragma unroll
                for (int hf = 0; hf < 2; hf++) {
                    uint32_t hh, ll;
                    split2(sp[2 * hf], sp[2 * hf + 1], hh, ll);
                    ph[2 * u + hf] = hh;
                    pl[2 * u + hf] = ll;
                }
            }
#pragma unroll
            for (int dimc = 0; dimc < 4; dimc++) {
                uint32_t vh[4], vl[4];
                ldsm4t(vh, sb + AV_HI + v_off + (uint32_t)(kk * 16) * ASTR + dimc * 32);
                ldsm4t(vl, sb + AV_LO + v_off + (uint32_t)(kk * 16) * ASTR + dimc * 32);
                mma16816(O[2 * dimc],     pl, &vh[0]);
                mma16816(O[2 * dimc],     ph, &vl[0]);
                mma16816(O[2 * dimc],     ph, &vh[0]);
                mma16816(O[2 * dimc + 1], pl, &vh[2]);
                mma16816(O[2 * dimc + 1], ph, &vl[2]);
                mma16816(O[2 * dimc + 1], ph, &vh[2]);
            }
        }

        __syncthreads();
        if (more) {
#pragma unroll
            for (int i = 0; i < 4; i++) {
                uint32_t o = (uint32_t)(kr0 + 16 * i) * ASTR + c4 * 8;
                cvt_store8(sm + AK_HI, sm + AK_LO, o, kreg[i]);
                cvt_store8(sm + AV_HI, sm + AV_LO, o, vreg[i]);
            }
            __syncthreads();
        }
    }

    const float invA = 1.f / lA, invB = 1.f / lB;
    const size_t rowA = (size_t)b * SS + qt * 128 + w * 16 + (lane >> 2);
    float* oA = out + rowA * EE + h * 64 + (lane & 3) * 2;
    float* oB = oA + (size_t)8 * EE;
#pragma unroll
    for (int j = 0; j < 8; j++) {
        *(float2*)(oA + j * 8) = make_float2(O[j][0] * invA, O[j][1] * invA);
        *(float2*)(oB + j * 8) = make_float2(O[j][2] * invB, O[j][3] * invB);
    }
}

// ---------------------------------------------------------------------------
// LayerNorm (R5-identical)
// ---------------------------------------------------------------------------
__global__ __launch_bounds__(256)
void ln_kernel(const float* __restrict__ r, const float* __restrict__ g,
               const float* __restrict__ be, float* __restrict__ out)
{
    const int row = blockIdx.x;
    const int tid = threadIdx.x;
    const int lane = tid & 31, warp = tid >> 5;

    float4 v = ((const float4*)(r + (size_t)row * EE))[tid];
    float s  = v.x + v.y + v.z + v.w;
    float sq = v.x * v.x + v.y * v.y + v.z * v.z + v.w * v.w;
#pragma unroll
    for (int o = 16; o; o >>= 1) {
        s  += __shfl_xor_sync(0xffffffffu, s,  o);
        sq += __shfl_xor_sync(0xffffffffu, sq, o);
    }
    __shared__ float ss[8], ssq[8];
    if (lane == 0) { ss[warp] = s; ssq[warp] = sq; }
    __syncthreads();
    float ts = 0.f, tq = 0.f;
#pragma unroll
    for (int i = 0; i < 8; i++) { ts += ss[i]; tq += ssq[i]; }
    float mu   = ts * (1.0f / EE);
    float var  = tq * (1.0f / EE) - mu * mu;
    float rstd = rsqrtf(var + 1e-5f);

    float4 gv = ((const float4*)g)[tid];
    float4 bv = ((const float4*)be)[tid];
    float4 o;
    o.x = (v.x - mu) * rstd * gv.x + bv.x;
    o.y = (v.y - mu) * rstd * gv.y + bv.y;
    o.z = (v.z - mu) * rstd * gv.z + bv.z;
    o.w = (v.w - mu) * rstd * gv.w + bv.w;
    ((float4*)(out + (size_t)row * EE))[tid] = o;
}

// ---------------------------------------------------------------------------
// Launch
// ---------------------------------------------------------------------------
extern "C" void kernel_launch(void* const* d_in, const int* in_sizes, int n_in,
                              void* d_out, int out_size)
{
    (void)in_sizes; (void)n_in; (void)out_size;
    const float* x     = (const float*)d_in[0];
    const float* w_qkv = (const float*)d_in[1];
    const float* b_qkv = (const float*)d_in[2];
    const float* w_out = (const float*)d_in[3];
    const float* b_out = (const float*)d_in[4];
    const float* w1    = (const float*)d_in[5];
    const float* b1    = (const float*)d_in[6];
    const float* w2    = (const float*)d_in[7];
    const float* b2    = (const float*)d_in[8];
    const float* g1    = (const float*)d_in[9];
    const float* be1   = (const float*)d_in[10];
    const float* g2    = (const float*)d_in[11];
    const float* be2   = (const float*)d_in[12];
    float* out = (float*)d_out;

    float *p_qkv, *p_att, *p_r1, *p_x1, *p_h, *p_r2;
    bf16 *p_wqh, *p_wql, *p_woh, *p_wol, *p_w1h, *p_w1l, *p_w2h, *p_w2l;
    cudaGetSymbolAddress((void**)&p_qkv, g_qkv);
    cudaGetSymbolAddress((void**)&p_att, g_att);
    cudaGetSymbolAddress((void**)&p_r1,  g_r1);
    cudaGetSymbolAddress((void**)&p_x1,  g_x1);
    cudaGetSymbolAddress((void**)&p_h,   g_h);
    cudaGetSymbolAddress((void**)&p_r2,  g_r2);
    cudaGetSymbolAddress((void**)&p_wqh, g_wqkv_h);
    cudaGetSymbolAddress((void**)&p_wql, g_wqkv_l);
    cudaGetSymbolAddress((void**)&p_woh, g_wout_h);
    cudaGetSymbolAddress((void**)&p_wol, g_wout_l);
    cudaGetSymbolAddress((void**)&p_w1h, g_w1_h);
    cudaGetSymbolAddress((void**)&p_w1l, g_w1_l);
    cudaGetSymbolAddress((void**)&p_w2h, g_w2_h);
    cudaGetSymbolAddress((void**)&p_w2l, g_w2_l);

    cudaFuncSetAttribute(attn_mma, cudaFuncAttributeMaxDynamicSharedMemorySize, ATT_SMEM);
    cudaFuncSetAttribute(gemm_hy<false, false>, cudaFuncAttributeMaxDynamicSharedMemorySize, GSM_TOTAL);
    cudaFuncSetAttribute(gemm_hy<false, true>,  cudaFuncAttributeMaxDynamicSharedMemorySize, GSM_TOTAL);
    cudaFuncSetAttribute(gemm_hy<true,  false>, cudaFuncAttributeMaxDynamicSharedMemorySize, GSM_TOTAL);

    // 0) split weights to bf16 hi/lo (once per replay; ~17us)
    split_kernel<<<(3 * EE * EE / 4) / 256, 256>>>(w_qkv, p_wqh, p_wql, 3 * EE * EE / 4);
    split_kernel<<<(EE * EE / 4) / 256, 256>>>(w_out, p_woh, p_wol, EE * EE / 4);
    split_kernel<<<(FFD * EE / 4) / 256, 256>>>(w1, p_w1h, p_w1l, FFD * EE / 4);
    split_kernel<<<(EE * FFD / 4) / 256, 256>>>(w2, p_w2h, p_w2l, EE * FFD / 4);

    // 1) QKV projection
    gemm_hy<false, false><<<dim3(3 * EE / 128, MR / 128), 256, GSM_TOTAL>>>(
        x, p_wqh, p_wql, b_qkv, nullptr, p_qkv, 3 * EE, EE);

    // 2) attention
    attn_mma<<<dim3(SS / 128, BB * HHN), 256, ATT_SMEM>>>(p_qkv, p_att);

    // 3) out-proj + residual(x)
    gemm_hy<false, true><<<dim3(EE / 128, MR / 128), 256, GSM_TOTAL>>>(
        p_att, p_woh, p_wol, b_out, x, p_r1, EE, EE);

    // 4) LN1
    ln_kernel<<<MR, 256>>>(p_r1, g1, be1, p_x1);

    // 5) FFN up + ReLU
    gemm_hy<true, false><<<dim3(FFD / 128, MR / 128), 256, GSM_TOTAL>>>(
        p_x1, p_w1h, p_w1l, b1, nullptr, p_h, FFD, EE);

    // 6) FFN down + residual(x1)
    gemm_hy<false, true><<<dim3(EE / 128, MR / 128), 256, GSM_TOTAL>>>(
        p_h, p_w2h, p_w2l, b2, p_x1, p_r2, EE, FFD);

    // 7) LN2
    ln_kernel<<<MR, 256>>>(p_r2, g2, be2, out);
}

// round 10
// speedup vs baseline: 1.1681x; 1.0422x over previous
#include <cuda_runtime.h>
#include <cuda_bf16.h>
#include <cstdint>
#include <math.h>

// Problem constants
#define BB   4
#define SS   2048
#define EE   1024
#define HHN  16
#define DKH  64
#define FFD  4096
#define MR   (BB*SS)   /* 8192 rows */

// ---------------------------------------------------------------------------
// Scratch
// ---------------------------------------------------------------------------
__device__ float g_qkv[(size_t)MR * 3 * EE];   // 96 MB
__device__ float g_att[(size_t)MR * EE];       // 32 MB
__device__ float g_r1 [(size_t)MR * EE];       // 32 MB
__device__ float g_x1 [(size_t)MR * EE];       // 32 MB
__device__ float g_h  [(size_t)MR * FFD];      // 128 MB
__device__ float g_r2 [(size_t)MR * EE];       // 32 MB

// ---------------------------------------------------------------------------
// Helpers
// ---------------------------------------------------------------------------
__device__ __forceinline__ uint32_t smem_u32(const void* p) {
    uint32_t a;
    asm("{ .reg .u64 t; cvta.to.shared.u64 t, %1; cvt.u32.u64 %0, t; }"
        : "=r"(a) : "l"(p));
    return a;
}

__device__ __forceinline__ void mma16816(float* c, const uint32_t* a, const uint32_t* b) {
    asm volatile(
        "mma.sync.aligned.m16n8k16.row.col.f32.bf16.bf16.f32 "
        "{%0,%1,%2,%3}, {%4,%5,%6,%7}, {%8,%9}, {%0,%1,%2,%3};"
        : "+f"(c[0]), "+f"(c[1]), "+f"(c[2]), "+f"(c[3])
        : "r"(a[0]), "r"(a[1]), "r"(a[2]), "r"(a[3]), "r"(b[0]), "r"(b[1]));
}

__device__ __forceinline__ void ldsm4(uint32_t* r, uint32_t addr) {
    asm volatile("ldmatrix.sync.aligned.m8n8.x4.shared.b16 {%0,%1,%2,%3}, [%4];"
        : "=r"(r[0]), "=r"(r[1]), "=r"(r[2]), "=r"(r[3]) : "r"(addr));
}

__device__ __forceinline__ void ldsm4t(uint32_t* r, uint32_t addr) {
    asm volatile("ldmatrix.sync.aligned.m8n8.x4.trans.shared.b16 {%0,%1,%2,%3}, [%4];"
        : "=r"(r[0]), "=r"(r[1]), "=r"(r[2]), "=r"(r[3]) : "r"(addr));
}

__device__ __forceinline__ void split2(float a, float b, uint32_t& hh, uint32_t& ll) {
    asm("cvt.rn.bf16x2.f32 %0,%1,%2;" : "=r"(hh) : "f"(b), "f"(a));
    float ra = a - __uint_as_float(hh << 16);
    float rb = b - __uint_as_float(hh & 0xFFFF0000u);
    asm("cvt.rn.bf16x2.f32 %0,%1,%2;" : "=r"(ll) : "f"(rb), "f"(ra));
}

__device__ __forceinline__ void cvt_store8(char* hi, char* lo, uint32_t boff, float4 v) {
    uint32_t h0, h1, l0, l1;
    split2(v.x, v.y, h0, l0);
    split2(v.z, v.w, h1, l1);
    *(uint2*)(hi + boff) = make_uint2(h0, h1);
    *(uint2*)(lo + boff) = make_uint2(l0, l1);
}

// ---------------------------------------------------------------------------
// GEMM via mma.sync, bf16 3-pass split: C[M,N] = A[M,K] @ W[N,K]^T
// CTA tile 256x128, BK=32, 256 thr (8 warps = 2M x 4N, warp tile 128x32).
// R5-style fp32 loads staged in registers, convert+store after MMA block.
// ---------------------------------------------------------------------------
#define SBYTE 80
#define TILE_A_HI 0
#define TILE_A_LO 20480
#define TILE_B_HI 40960
#define TILE_B_LO 51200
#define STAGE     61440
#define GSM_TOTAL (2 * STAGE)

template<bool RELU, bool RES>
__global__ __launch_bounds__(256, 1)
void gemm_mma(const float* __restrict__ A, const float* __restrict__ W,
              const float* __restrict__ bias, const float* __restrict__ res,
              float* __restrict__ C, int N, int K)
{
    extern __shared__ char sm[];
    const int tid = threadIdx.x, lane = tid & 31, wid = tid >> 5;
    const int wm = wid & 1;        // 0..1 : M half (128 rows)
    const int wn = wid >> 1;       // 0..3 : N quarter (32 cols)
    const int bm = blockIdx.y * 256, bn = blockIdx.x * 128;
    const uint32_t sbase = smem_u32(sm);

    const uint32_t a_off = (uint32_t)(wm * 128 + (lane & 15)) * SBYTE + ((lane >> 4) * 16);
    const uint32_t b_off = (uint32_t)(wn * 32 + (lane & 7) + ((lane >> 4) << 3)) * SBYTE
                         + (((lane >> 3) & 1) * 16);

    // loaders: fixed float4 column c4, rows r0 + 32*i
    const int c4 = tid & 7, r0 = tid >> 3;
    const float* Ap = A + (size_t)(bm + r0) * K + c4 * 4;
    const float* Wp = W + (size_t)(bn + r0) * K + c4 * 4;
    const uint32_t st_off = (uint32_t)r0 * SBYTE + c4 * 8;

    float acc[8][4][4];
#pragma unroll
    for (int mt = 0; mt < 8; mt++)
#pragma unroll
        for (int nt = 0; nt < 4; nt++)
#pragma unroll
            for (int j = 0; j < 4; j++) acc[mt][nt][j] = 0.f;

    float4 va[8], vb[4];
#pragma unroll
    for (int i = 0; i < 8; i++)
        va[i] = *(const float4*)(Ap + (size_t)(32 * i) * K);
#pragma unroll
    for (int i = 0; i < 4; i++)
        vb[i] = *(const float4*)(Wp + (size_t)(32 * i) * K);
#pragma unroll
    for (int i = 0; i < 8; i++)
        cvt_store8(sm + TILE_A_HI, sm + TILE_A_LO, st_off + i * 32 * SBYTE, va[i]);
#pragma unroll
    for (int i = 0; i < 4; i++)
        cvt_store8(sm + TILE_B_HI, sm + TILE_B_LO, st_off + i * 32 * SBYTE, vb[i]);
    __syncthreads();

    const int KT = K >> 5;
    for (int kt = 0; kt < KT; kt++) {
        if (kt + 1 < KT) {
#pragma unroll
            for (int i = 0; i < 8; i++)
                va[i] = *(const float4*)(Ap + (size_t)(32 * i) * K + (kt + 1) * 32);
#pragma unroll
            for (int i = 0; i < 4; i++)
                vb[i] = *(const float4*)(Wp + (size_t)(32 * i) * K + (kt + 1) * 32);
        }
        const uint32_t base = sbase + (kt & 1) * STAGE;
#pragma unroll
        for (int ks = 0; ks < 2; ks++) {
            uint32_t bh[2][4], bl[2][4];
#pragma unroll
            for (int i = 0; i < 2; i++) {
                ldsm4(bh[i], base + TILE_B_HI + b_off + i * (16 * SBYTE) + ks * 32);
                ldsm4(bl[i], base + TILE_B_LO + b_off + i * (16 * SBYTE) + ks * 32);
            }
#pragma unroll
            for (int mt = 0; mt < 8; mt++) {
                uint32_t ah[4], al[4];
                ldsm4(ah, base + TILE_A_HI + a_off + mt * (16 * SBYTE) + ks * 32);
                ldsm4(al, base + TILE_A_LO + a_off + mt * (16 * SBYTE) + ks * 32);
#pragma unroll
                for (int nt = 0; nt < 4; nt++) {
                    const uint32_t* bph = &bh[nt >> 1][(nt & 1) * 2];
                    const uint32_t* bpl = &bl[nt >> 1][(nt & 1) * 2];
                    mma16816(acc[mt][nt], al, bph);
                    mma16816(acc[mt][nt], ah, bpl);
                    mma16816(acc[mt][nt], ah, bph);
                }
            }
        }
        if (kt + 1 < KT) {
            char* nb = sm + ((kt + 1) & 1) * STAGE;
#pragma unroll
            for (int i = 0; i < 8; i++)
                cvt_store8(nb + TILE_A_HI, nb + TILE_A_LO, st_off + i * 32 * SBYTE, va[i]);
#pragma unroll
            for (int i = 0; i < 4; i++)
                cvt_store8(nb + TILE_B_HI, nb + TILE_B_LO, st_off + i * 32 * SBYTE, vb[i]);
        }
        __syncthreads();
    }

    // Epilogue
    const int erow = bm + wm * 128 + (lane >> 2);
    const int ecol = bn + wn * 32 + (lane & 3) * 2;
#pragma unroll
    for (int mt = 0; mt < 8; mt++)
#pragma unroll
        for (int nt = 0; nt < 4; nt++) {
            const int col = ecol + nt * 8;
            float2 bv = *(const float2*)(bias + col);
#pragma unroll
            for (int h2 = 0; h2 < 2; h2++) {
                const int row = erow + mt * 16 + h2 * 8;
                float o0 = acc[mt][nt][h2 * 2 + 0] + bv.x;
                float o1 = acc[mt][nt][h2 * 2 + 1] + bv.y;
                if (RES) {
                    float2 rv = *(const float2*)(res + (size_t)row * N + col);
                    o0 += rv.x; o1 += rv.y;
                }
                if (RELU) { o0 = fmaxf(o0, 0.f); o1 = fmaxf(o1, 0.f); }
                *(float2*)(C + (size_t)row * N + col) = make_float2(o0, o1);
            }
        }
}

// ---------------------------------------------------------------------------
// Flash attention via mma.sync (R5-identical)
// ---------------------------------------------------------------------------
#define ASTR   144
#define AQ_HI  0
#define AQ_LO  (128 * ASTR)
#define AK_HI  (2 * 128 * ASTR)
#define AK_LO  (AK_HI + 64 * ASTR)
#define AV_HI  (AK_LO + 64 * ASTR)
#define AV_LO  (AV_HI + 64 * ASTR)
#define ATT_SMEM (AV_LO + 64 * ASTR)   /* 73728 */

__global__ __launch_bounds__(256, 1)
void attn_mma(const float* __restrict__ qkv, float* __restrict__ out)
{
    extern __shared__ char sm[];
    const uint32_t sb = smem_u32(sm);
    const int tid = threadIdx.x, lane = tid & 31, w = tid >> 5;
    const int qt = blockIdx.x;
    const int bh = blockIdx.y;
    const int b = bh >> 4, h = bh & 15;

    const float* base = qkv + (size_t)b * SS * (3 * EE);

    {
        const int c4q = tid & 15, r0q = tid >> 4;
#pragma unroll
        for (int i = 0; i < 8; i++) {
            int r = r0q + 16 * i;
            float4 v = *(const float4*)(base + (size_t)(qt * 128 + r) * (3 * EE) + h * 64 + c4q * 4);
            v.x *= 0.125f; v.y *= 0.125f; v.z *= 0.125f; v.w *= 0.125f;
            cvt_store8(sm + AQ_HI, sm + AQ_LO, (uint32_t)r * ASTR + c4q * 8, v);
        }
    }

    const int c4 = tid & 15, kr0 = tid >> 4;
    const float* kbase = base + EE + h * 64 + c4 * 4;
    const float* vbase = kbase + EE;

    float4 kreg[4], vreg[4];
#pragma unroll
    for (int i = 0; i < 4; i++) {
        kreg[i] = *(const float4*)(kbase + (size_t)(kr0 + 16 * i) * (3 * EE));
        vreg[i] = *(const float4*)(vbase + (size_t)(kr0 + 16 * i) * (3 * EE));
    }
#pragma unroll
    for (int i = 0; i < 4; i++) {
        uint32_t o = (uint32_t)(kr0 + 16 * i) * ASTR + c4 * 8;
        cvt_store8(sm + AK_HI, sm + AK_LO, o, kreg[i]);
        cvt_store8(sm + AV_HI, sm + AV_LO, o, vreg[i]);
    }
    __syncthreads();

    const uint32_t a_off = (uint32_t)(w * 16 + (lane & 15)) * ASTR + ((lane >> 4) * 16);
    const uint32_t b_off = (uint32_t)((lane & 7) + ((lane >> 4) << 3)) * ASTR
                         + (((lane >> 3) & 1) * 16);
    const uint32_t v_off = (uint32_t)(lane & 15) * ASTR + ((lane >> 4) * 16);

    float mA = -1e30f, mB = -1e30f, lA = 0.f, lB = 0.f;
    float O[8][4];
#pragma unroll
    for (int j = 0; j < 8; j++)
#pragma unroll
        for (int k = 0; k < 4; k++) O[j][k] = 0.f;

    const int NT = SS / 64;
    for (int kt = 0; kt < NT; kt++) {
        const bool more = (kt + 1 < NT);
        if (more) {
#pragma unroll
            for (int i = 0; i < 4; i++) {
                kreg[i] = *(const float4*)(kbase + (size_t)((kt + 1) * 64 + kr0 + 16 * i) * (3 * EE));
                vreg[i] = *(const float4*)(vbase + (size_t)((kt + 1) * 64 + kr0 + 16 * i) * (3 * EE));
            }
        }

        float S[8][4];
#pragma unroll
        for (int j = 0; j < 8; j++)
#pragma unroll
            for (int k = 0; k < 4; k++) S[j][k] = 0.f;

#pragma unroll
        for (int kd = 0; kd < 4; kd++) {
            uint32_t ah[4], al[4];
            ldsm4(ah, sb + AQ_HI + a_off + kd * 32);
            ldsm4(al, sb + AQ_LO + a_off + kd * 32);
#pragma unroll
            for (int i = 0; i < 4; i++) {
                uint32_t bh4[4], bl4[4];
                ldsm4(bh4, sb + AK_HI + b_off + i * (16 * ASTR) + kd * 32);
                ldsm4(bl4, sb + AK_LO + b_off + i * (16 * ASTR) + kd * 32);
                mma16816(S[2 * i],     al, &bh4[0]);
                mma16816(S[2 * i],     ah, &bl4[0]);
                mma16816(S[2 * i],     ah, &bh4[0]);
                mma16816(S[2 * i + 1], al, &bh4[2]);
                mma16816(S[2 * i + 1], ah, &bl4[2]);
                mma16816(S[2 * i + 1], ah, &bh4[2]);
            }
        }

        float txA = -1e30f, txB = -1e30f;
#pragma unroll
        for (int j = 0; j < 8; j++) {
            txA = fmaxf(txA, fmaxf(S[j][0], S[j][1]));
            txB = fmaxf(txB, fmaxf(S[j][2], S[j][3]));
        }
        txA = fmaxf(txA, __shfl_xor_sync(0xffffffffu, txA, 1));
        txA = fmaxf(txA, __shfl_xor_sync(0xffffffffu, txA, 2));
        txB = fmaxf(txB, __shfl_xor_sync(0xffffffffu, txB, 1));
        txB = fmaxf(txB, __shfl_xor_sync(0xffffffffu, txB, 2));
        const float mnA = fmaxf(mA, txA), mnB = fmaxf(mB, txB);
        const float cA = __expf(mA - mnA), cB = __expf(mB - mnB);

        float sA = 0.f, sB = 0.f;
#pragma unroll
        for (int j = 0; j < 8; j++) {
            S[j][0] = __expf(S[j][0] - mnA);
            S[j][1] = __expf(S[j][1] - mnA);
            S[j][2] = __expf(S[j][2] - mnB);
            S[j][3] = __expf(S[j][3] - mnB);
            sA += S[j][0] + S[j][1];
            sB += S[j][2] + S[j][3];
        }
        sA += __shfl_xor_sync(0xffffffffu, sA, 1);
        sA += __shfl_xor_sync(0xffffffffu, sA, 2);
        sB += __shfl_xor_sync(0xffffffffu, sB, 1);
        sB += __shfl_xor_sync(0xffffffffu, sB, 2);
        lA = lA * cA + sA;  mA = mnA;
        lB = lB * cB + sB;  mB = mnB;
#pragma unroll
        for (int j = 0; j < 8; j++) {
            O[j][0] *= cA; O[j][1] *= cA;
            O[j][2] *= cB; O[j][3] *= cB;
        }

#pragma unroll
        for (int kk = 0; kk < 4; kk++) {
            uint32_t ph[4], pl[4];
#pragma unroll
            for (int u = 0; u < 2; u++) {
                const float* sp = S[2 * kk + u];
#pragma unroll
                for (int hf = 0; hf < 2; hf++) {
                    uint32_t hh, ll;
                    split2(sp[2 * hf], sp[2 * hf + 1], hh, ll);
                    ph[2 * u + hf] = hh;
                    pl[2 * u + hf] = ll;
                }
            }
#pragma unroll
            for (int dimc = 0; dimc < 4; dimc++) {
                uint32_t vh[4], vl[4];
                ldsm4t(vh, sb + AV_HI + v_off + (uint32_t)(kk * 16) * ASTR + dimc * 32);
                ldsm4t(vl, sb + AV_LO + v_off + (uint32_t)(kk * 16) * ASTR + dimc * 32);
                mma16816(O[2 * dimc],     pl, &vh[0]);
                mma16816(O[2 * dimc],     ph, &vl[0]);
                mma16816(O[2 * dimc],     ph, &vh[0]);
                mma16816(O[2 * dimc + 1], pl, &vh[2]);
                mma16816(O[2 * dimc + 1], ph, &vl[2]);
                mma16816(O[2 * dimc + 1], ph, &vh[2]);
            }
        }

        __syncthreads();
        if (more) {
#pragma unroll
            for (int i = 0; i < 4; i++) {
                uint32_t o = (uint32_t)(kr0 + 16 * i) * ASTR + c4 * 8;
                cvt_store8(sm + AK_HI, sm + AK_LO, o, kreg[i]);
                cvt_store8(sm + AV_HI, sm + AV_LO, o, vreg[i]);
            }
            __syncthreads();
        }
    }

    const float invA = 1.f / lA, invB = 1.f / lB;
    const size_t rowA = (size_t)b * SS + qt * 128 + w * 16 + (lane >> 2);
    float* oA = out + rowA * EE + h * 64 + (lane & 3) * 2;
    float* oB = oA + (size_t)8 * EE;
#pragma unroll
    for (int j = 0; j < 8; j++) {
        *(float2*)(oA + j * 8) = make_float2(O[j][0] * invA, O[j][1] * invA);
        *(float2*)(oB + j * 8) = make_float2(O[j][2] * invB, O[j][3] * invB);
    }
}

// ---------------------------------------------------------------------------
// LayerNorm (unchanged)
// ---------------------------------------------------------------------------
__global__ __launch_bounds__(256)
void ln_kernel(const float* __restrict__ r, const float* __restrict__ g,
               const float* __restrict__ be, float* __restrict__ out)
{
    const int row = blockIdx.x;
    const int tid = threadIdx.x;
    const int lane = tid & 31, warp = tid >> 5;

    float4 v = ((const float4*)(r + (size_t)row * EE))[tid];
    float s  = v.x + v.y + v.z + v.w;
    float sq = v.x * v.x + v.y * v.y + v.z * v.z + v.w * v.w;
#pragma unroll
    for (int o = 16; o; o >>= 1) {
        s  += __shfl_xor_sync(0xffffffffu, s,  o);
        sq += __shfl_xor_sync(0xffffffffu, sq, o);
    }
    __shared__ float ss[8], ssq[8];
    if (lane == 0) { ss[warp] = s; ssq[warp] = sq; }
    __syncthreads();
    float ts = 0.f, tq = 0.f;
#pragma unroll
    for (int i = 0; i < 8; i++) { ts += ss[i]; tq += ssq[i]; }
    float mu   = ts * (1.0f / EE);
    float var  = tq * (1.0f / EE) - mu * mu;
    float rstd = rsqrtf(var + 1e-5f);

    float4 gv = ((const float4*)g)[tid];
    float4 bv = ((const float4*)be)[tid];
    float4 o;
    o.x = (v.x - mu) * rstd * gv.x + bv.x;
    o.y = (v.y - mu) * rstd * gv.y + bv.y;
    o.z = (v.z - mu) * rstd * gv.z + bv.z;
    o.w = (v.w - mu) * rstd * gv.w + bv.w;
    ((float4*)(out + (size_t)row * EE))[tid] = o;
}

// ---------------------------------------------------------------------------
// Launch
// ---------------------------------------------------------------------------
extern "C" void kernel_launch(void* const* d_in, const int* in_sizes, int n_in,
                              void* d_out, int out_size)
{
    (void)in_sizes; (void)n_in; (void)out_size;
    const float* x     = (const float*)d_in[0];
    const float* w_qkv = (const float*)d_in[1];
    const float* b_qkv = (const float*)d_in[2];
    const float* w_out = (const float*)d_in[3];
    const float* b_out = (const float*)d_in[4];
    const float* w1    = (const float*)d_in[5];
    const float* b1    = (const float*)d_in[6];
    const float* w2    = (const float*)d_in[7];
    const float* b2    = (const float*)d_in[8];
    const float* g1    = (const float*)d_in[9];
    const float* be1   = (const float*)d_in[10];
    const float* g2    = (const float*)d_in[11];
    const float* be2   = (const float*)d_in[12];
    float* out = (float*)d_out;

    float *p_qkv, *p_att, *p_r1, *p_x1, *p_h, *p_r2;
    cudaGetSymbolAddress((void**)&p_qkv, g_qkv);
    cudaGetSymbolAddress((void**)&p_att, g_att);
    cudaGetSymbolAddress((void**)&p_r1,  g_r1);
    cudaGetSymbolAddress((void**)&p_x1,  g_x1);
    cudaGetSymbolAddress((void**)&p_h,   g_h);
    cudaGetSymbolAddress((void**)&p_r2,  g_r2);

    cudaFuncSetAttribute(attn_mma, cudaFuncAttributeMaxDynamicSharedMemorySize, ATT_SMEM);
    cudaFuncSetAttribute(gemm_mma<false, false>, cudaFuncAttributeMaxDynamicSharedMemorySize, GSM_TOTAL);
    cudaFuncSetAttribute(gemm_mma<false, true>,  cudaFuncAttributeMaxDynamicSharedMemorySize, GSM_TOTAL);
    cudaFuncSetAttribute(gemm_mma<true,  false>, cudaFuncAttributeMaxDynamicSharedMemorySize, GSM_TOTAL);

    // 1) QKV projection: [8192,1024] @ [3072,1024]^T
    gemm_mma<false, false><<<dim3(3 * EE / 128, MR / 256), 256, GSM_TOTAL>>>(
        x, w_qkv, b_qkv, nullptr, p_qkv, 3 * EE, EE);

    // 2) attention
    attn_mma<<<dim3(SS / 128, BB * HHN), 256, ATT_SMEM>>>(p_qkv, p_att);

    // 3) out-proj + residual(x)
    gemm_mma<false, true><<<dim3(EE / 128, MR / 256), 256, GSM_TOTAL>>>(
        p_att, w_out, b_out, x, p_r1, EE, EE);

    // 4) LN1
    ln_kernel<<<MR, 256>>>(p_r1, g1, be1, p_x1);

    // 5) FFN up + ReLU
    gemm_mma<true, false><<<dim3(FFD / 128, MR / 256), 256, GSM_TOTAL>>>(
        p_x1, w1, b1, nullptr, p_h, FFD, EE);

    // 6) FFN down + residual(x1)
    gemm_mma<false, true><<<dim3(EE / 128, MR / 256), 256, GSM_TOTAL>>>(
        p_h, w2, b2, p_x1, p_r2, EE, FFD);

    // 7) LN2
    ln_kernel<<<MR, 256>>>(p_r2, g2, be2, out);
}

// round 11
// speedup vs baseline: 1.4330x; 1.2268x over previous
#include <cuda_runtime.h>
#include <cuda_bf16.h>
#include <cuda_fp16.h>
#include <cstdint>
#include <math.h>

// Problem constants
#define BB   4
#define SS   2048
#define EE   1024
#define HHN  16
#define DKH  64
#define FFD  4096
#define MR   (BB*SS)   /* 8192 rows */

// ---------------------------------------------------------------------------
// Scratch
// ---------------------------------------------------------------------------
__device__ float g_qkv[(size_t)MR * 3 * EE];   // 96 MB
__device__ float g_att[(size_t)MR * EE];       // 32 MB
__device__ float g_r1 [(size_t)MR * EE];       // 32 MB
__device__ float g_x1 [(size_t)MR * EE];       // 32 MB
__device__ float g_h  [(size_t)MR * FFD];      // 128 MB
__device__ float g_r2 [(size_t)MR * EE];       // 32 MB

// ---------------------------------------------------------------------------
// Helpers
// ---------------------------------------------------------------------------
__device__ __forceinline__ uint32_t smem_u32(const void* p) {
    uint32_t a;
    asm("{ .reg .u64 t; cvta.to.shared.u64 t, %1; cvt.u32.u64 %0, t; }"
        : "=r"(a) : "l"(p));
    return a;
}

// bf16 mma (attention path)
__device__ __forceinline__ void mma16816(float* c, const uint32_t* a, const uint32_t* b) {
    asm volatile(
        "mma.sync.aligned.m16n8k16.row.col.f32.bf16.bf16.f32 "
        "{%0,%1,%2,%3}, {%4,%5,%6,%7}, {%8,%9}, {%0,%1,%2,%3};"
        : "+f"(c[0]), "+f"(c[1]), "+f"(c[2]), "+f"(c[3])
        : "r"(a[0]), "r"(a[1]), "r"(a[2]), "r"(a[3]), "r"(b[0]), "r"(b[1]));
}

// fp16 mma (GEMM path)
__device__ __forceinline__ void mma16816h(float* c, const uint32_t* a, const uint32_t* b) {
    asm volatile(
        "mma.sync.aligned.m16n8k16.row.col.f32.f16.f16.f32 "
        "{%0,%1,%2,%3}, {%4,%5,%6,%7}, {%8,%9}, {%0,%1,%2,%3};"
        : "+f"(c[0]), "+f"(c[1]), "+f"(c[2]), "+f"(c[3])
        : "r"(a[0]), "r"(a[1]), "r"(a[2]), "r"(a[3]), "r"(b[0]), "r"(b[1]));
}

__device__ __forceinline__ void ldsm4(uint32_t* r, uint32_t addr) {
    asm volatile("ldmatrix.sync.aligned.m8n8.x4.shared.b16 {%0,%1,%2,%3}, [%4];"
        : "=r"(r[0]), "=r"(r[1]), "=r"(r[2]), "=r"(r[3]) : "r"(addr));
}

__device__ __forceinline__ void ldsm4t(uint32_t* r, uint32_t addr) {
    asm volatile("ldmatrix.sync.aligned.m8n8.x4.trans.shared.b16 {%0,%1,%2,%3}, [%4];"
        : "=r"(r[0]), "=r"(r[1]), "=r"(r[2]), "=r"(r[3]) : "r"(addr));
}

// bf16 split pair (attention)
__device__ __forceinline__ void split2(float a, float b, uint32_t& hh, uint32_t& ll) {
    asm("cvt.rn.bf16x2.f32 %0,%1,%2;" : "=r"(hh) : "f"(b), "f"(a));
    float ra = a - __uint_as_float(hh << 16);
    float rb = b - __uint_as_float(hh & 0xFFFF0000u);
    asm("cvt.rn.bf16x2.f32 %0,%1,%2;" : "=r"(ll) : "f"(rb), "f"(ra));
}

__device__ __forceinline__ void cvt_store8(char* hi, char* lo, uint32_t boff, float4 v) {
    uint32_t h0, h1, l0, l1;
    split2(v.x, v.y, h0, l0);
    split2(v.z, v.w, h1, l1);
    *(uint2*)(hi + boff) = make_uint2(h0, h1);
    *(uint2*)(lo + boff) = make_uint2(l0, l1);
}

// fp16 exact 2-term split of 4 floats -> hi/lo tiles
__device__ __forceinline__ void cvt_store8_f16split(char* hi, char* lo, uint32_t boff, float4 v) {
    __half2 h0 = __floats2half2_rn(v.x, v.y);
    __half2 h1 = __floats2half2_rn(v.z, v.w);
    float2 f0 = __half22float2(h0);
    float2 f1 = __half22float2(h1);
    __half2 l0 = __floats2half2_rn(v.x - f0.x, v.y - f0.y);
    __half2 l1 = __floats2half2_rn(v.z - f1.x, v.w - f1.y);
    *(uint2*)(hi + boff) = make_uint2(*(uint32_t*)&h0, *(uint32_t*)&h1);
    *(uint2*)(lo + boff) = make_uint2(*(uint32_t*)&l0, *(uint32_t*)&l1);
}

// fp16 single rounding of 4 floats -> one tile
__device__ __forceinline__ void cvt_store8_f16(char* dst, uint32_t boff, float4 v) {
    __half2 h0 = __floats2half2_rn(v.x, v.y);
    __half2 h1 = __floats2half2_rn(v.z, v.w);
    *(uint2*)(dst + boff) = make_uint2(*(uint32_t*)&h0, *(uint32_t*)&h1);
}

// ---------------------------------------------------------------------------
// GEMM via mma.sync fp16 2-pass: C = (Ah+Al) @ f16(W)^T (+bias,res,relu)
// CTA tile 128x128, BK=32, 256 thr (2M x 4N warps), double-buffered.
// R5 loader structure (fp32 LDG staged in regs, cvt+STS after MMA block).
// ---------------------------------------------------------------------------
#define SBYTE 80
#define TILE_A_HI 0
#define TILE_A_LO 10240
#define TILE_B    20480
#define STAGE     30720
#define GSM_TOTAL (2 * STAGE)

template<bool RELU, bool RES>
__global__ __launch_bounds__(256, 1)
void gemm_mma(const float* __restrict__ A, const float* __restrict__ W,
              const float* __restrict__ bias, const float* __restrict__ res,
              float* __restrict__ C, int N, int K)
{
    extern __shared__ char sm[];
    const int tid = threadIdx.x, lane = tid & 31, wid = tid >> 5;
    const int wm = wid & 1;
    const int wn = wid >> 1;
    const int bm = blockIdx.y * 128, bn = blockIdx.x * 128;
    const uint32_t sbase = smem_u32(sm);

    const uint32_t a_off = (uint32_t)(wm * 64 + (lane & 15)) * SBYTE + ((lane >> 4) * 16);
    const uint32_t b_off = (uint32_t)(wn * 32 + (lane & 7) + ((lane >> 4) << 3)) * SBYTE
                         + (((lane >> 3) & 1) * 16);

    const int c4 = tid & 7, r0 = tid >> 3;
    const float* Ap = A + (size_t)(bm + r0) * K + c4 * 4;
    const float* Wp = W + (size_t)(bn + r0) * K + c4 * 4;
    const uint32_t st_off = (uint32_t)r0 * SBYTE + c4 * 8;

    float acc[4][4][4];
#pragma unroll
    for (int mt = 0; mt < 4; mt++)
#pragma unroll
        for (int nt = 0; nt < 4; nt++)
#pragma unroll
            for (int j = 0; j < 4; j++) acc[mt][nt][j] = 0.f;

    float4 va[4], vb[4];
#pragma unroll
    for (int i = 0; i < 4; i++) {
        va[i] = *(const float4*)(Ap + (size_t)(32 * i) * K);
        vb[i] = *(const float4*)(Wp + (size_t)(32 * i) * K);
    }
#pragma unroll
    for (int i = 0; i < 4; i++) {
        uint32_t o = st_off + i * 32 * SBYTE;
        cvt_store8_f16split(sm + TILE_A_HI, sm + TILE_A_LO, o, va[i]);
        cvt_store8_f16(sm + TILE_B, o, vb[i]);
    }
    __syncthreads();

    const int KT = K >> 5;
    for (int kt = 0; kt < KT; kt++) {
        if (kt + 1 < KT) {
#pragma unroll
            for (int i = 0; i < 4; i++) {
                va[i] = *(const float4*)(Ap + (size_t)(32 * i) * K + (kt + 1) * 32);
                vb[i] = *(const float4*)(Wp + (size_t)(32 * i) * K + (kt + 1) * 32);
            }
        }
        const uint32_t base = sbase + (kt & 1) * STAGE;
#pragma unroll
        for (int ks = 0; ks < 2; ks++) {
            uint32_t ah[4][4], al[4][4], bh[2][4];
#pragma unroll
            for (int t = 0; t < 4; t++) {
                ldsm4(ah[t], base + TILE_A_HI + a_off + t * (16 * SBYTE) + ks * 32);
                ldsm4(al[t], base + TILE_A_LO + a_off + t * (16 * SBYTE) + ks * 32);
            }
#pragma unroll
            for (int i = 0; i < 2; i++)
                ldsm4(bh[i], base + TILE_B + b_off + i * (16 * SBYTE) + ks * 32);
#pragma unroll
            for (int mt = 0; mt < 4; mt++)
#pragma unroll
                for (int nt = 0; nt < 4; nt++) {
                    const uint32_t* bph = &bh[nt >> 1][(nt & 1) * 2];
                    mma16816h(acc[mt][nt], al[mt], bph);   // lo*W
                    mma16816h(acc[mt][nt], ah[mt], bph);   // hi*W
                }
        }
        if (kt + 1 < KT) {
            char* nb = sm + ((kt + 1) & 1) * STAGE;
#pragma unroll
            for (int i = 0; i < 4; i++) {
                uint32_t o = st_off + i * 32 * SBYTE;
                cvt_store8_f16split(nb + TILE_A_HI, nb + TILE_A_LO, o, va[i]);
                cvt_store8_f16(nb + TILE_B, o, vb[i]);
            }
        }
        __syncthreads();
    }

    // Epilogue (R5-identical)
    const int erow = bm + wm * 64 + (lane >> 2);
    const int ecol = bn + wn * 32 + (lane & 3) * 2;
#pragma unroll
    for (int mt = 0; mt < 4; mt++)
#pragma unroll
        for (int nt = 0; nt < 4; nt++) {
            const int col = ecol + nt * 8;
            float2 bv = *(const float2*)(bias + col);
#pragma unroll
            for (int h2 = 0; h2 < 2; h2++) {
                const int row = erow + mt * 16 + h2 * 8;
                float o0 = acc[mt][nt][h2 * 2 + 0] + bv.x;
                float o1 = acc[mt][nt][h2 * 2 + 1] + bv.y;
                if (RES) {
                    float2 rv = *(const float2*)(res + (size_t)row * N + col);
                    o0 += rv.x; o1 += rv.y;
                }
                if (RELU) { o0 = fmaxf(o0, 0.f); o1 = fmaxf(o1, 0.f); }
                *(float2*)(C + (size_t)row * N + col) = make_float2(o0, o1);
            }
        }
}

// ---------------------------------------------------------------------------
// Flash attention via mma.sync (R5-identical, bf16 3-pass)
// ---------------------------------------------------------------------------
#define ASTR   144
#define AQ_HI  0
#define AQ_LO  (128 * ASTR)
#define AK_HI  (2 * 128 * ASTR)
#define AK_LO  (AK_HI + 64 * ASTR)
#define AV_HI  (AK_LO + 64 * ASTR)
#define AV_LO  (AV_HI + 64 * ASTR)
#define ATT_SMEM (AV_LO + 64 * ASTR)   /* 73728 */

__global__ __launch_bounds__(256, 1)
void attn_mma(const float* __restrict__ qkv, float* __restrict__ out)
{
    extern __shared__ char sm[];
    const uint32_t sb = smem_u32(sm);
    const int tid = threadIdx.x, lane = tid & 31, w = tid >> 5;
    const int qt = blockIdx.x;
    const int bh = blockIdx.y;
    const int b = bh >> 4, h = bh & 15;

    const float* base = qkv + (size_t)b * SS * (3 * EE);

    {
        const int c4q = tid & 15, r0q = tid >> 4;
#pragma unroll
        for (int i = 0; i < 8; i++) {
            int r = r0q + 16 * i;
            float4 v = *(const float4*)(base + (size_t)(qt * 128 + r) * (3 * EE) + h * 64 + c4q * 4);
            v.x *= 0.125f; v.y *= 0.125f; v.z *= 0.125f; v.w *= 0.125f;
            cvt_store8(sm + AQ_HI, sm + AQ_LO, (uint32_t)r * ASTR + c4q * 8, v);
        }
    }

    const int c4 = tid & 15, kr0 = tid >> 4;
    const float* kbase = base + EE + h * 64 + c4 * 4;
    const float* vbase = kbase + EE;

    float4 kreg[4], vreg[4];
#pragma unroll
    for (int i = 0; i < 4; i++) {
        kreg[i] = *(const float4*)(kbase + (size_t)(kr0 + 16 * i) * (3 * EE));
        vreg[i] = *(const float4*)(vbase + (size_t)(kr0 + 16 * i) * (3 * EE));
    }
#pragma unroll
    for (int i = 0; i < 4; i++) {
        uint32_t o = (uint32_t)(kr0 + 16 * i) * ASTR + c4 * 8;
        cvt_store8(sm + AK_HI, sm + AK_LO, o, kreg[i]);
        cvt_store8(sm + AV_HI, sm + AV_LO, o, vreg[i]);
    }
    __syncthreads();

    const uint32_t a_off = (uint32_t)(w * 16 + (lane & 15)) * ASTR + ((lane >> 4) * 16);
    const uint32_t b_off = (uint32_t)((lane & 7) + ((lane >> 4) << 3)) * ASTR
                         + (((lane >> 3) & 1) * 16);
    const uint32_t v_off = (uint32_t)(lane & 15) * ASTR + ((lane >> 4) * 16);

    float mA = -1e30f, mB = -1e30f, lA = 0.f, lB = 0.f;
    float O[8][4];
#pragma unroll
    for (int j = 0; j < 8; j++)
#pragma unroll
        for (int k = 0; k < 4; k++) O[j][k] = 0.f;

    const int NT = SS / 64;
    for (int kt = 0; kt < NT; kt++) {
        const bool more = (kt + 1 < NT);
        if (more) {
#pragma unroll
            for (int i = 0; i < 4; i++) {
                kreg[i] = *(const float4*)(kbase + (size_t)((kt + 1) * 64 + kr0 + 16 * i) * (3 * EE));
                vreg[i] = *(const float4*)(vbase + (size_t)((kt + 1) * 64 + kr0 + 16 * i) * (3 * EE));
            }
        }

        float S[8][4];
#pragma unroll
        for (int j = 0; j < 8; j++)
#pragma unroll
            for (int k = 0; k < 4; k++) S[j][k] = 0.f;

#pragma unroll
        for (int kd = 0; kd < 4; kd++) {
            uint32_t ah[4], al[4];
            ldsm4(ah, sb + AQ_HI + a_off + kd * 32);
            ldsm4(al, sb + AQ_LO + a_off + kd * 32);
#pragma unroll
            for (int i = 0; i < 4; i++) {
                uint32_t bh4[4], bl4[4];
                ldsm4(bh4, sb + AK_HI + b_off + i * (16 * ASTR) + kd * 32);
                ldsm4(bl4, sb + AK_LO + b_off + i * (16 * ASTR) + kd * 32);
                mma16816(S[2 * i],     al, &bh4[0]);
                mma16816(S[2 * i],     ah, &bl4[0]);
                mma16816(S[2 * i],     ah, &bh4[0]);
                mma16816(S[2 * i + 1], al, &bh4[2]);
                mma16816(S[2 * i + 1], ah, &bl4[2]);
                mma16816(S[2 * i + 1], ah, &bh4[2]);
            }
        }

        float txA = -1e30f, txB = -1e30f;
#pragma unroll
        for (int j = 0; j < 8; j++) {
            txA = fmaxf(txA, fmaxf(S[j][0], S[j][1]));
            txB = fmaxf(txB, fmaxf(S[j][2], S[j][3]));
        }
        txA = fmaxf(txA, __shfl_xor_sync(0xffffffffu, txA, 1));
        txA = fmaxf(txA, __shfl_xor_sync(0xffffffffu, txA, 2));
        txB = fmaxf(txB, __shfl_xor_sync(0xffffffffu, txB, 1));
        txB = fmaxf(txB, __shfl_xor_sync(0xffffffffu, txB, 2));
        const float mnA = fmaxf(mA, txA), mnB = fmaxf(mB, txB);
        const float cA = __expf(mA - mnA), cB = __expf(mB - mnB);

        float sA = 0.f, sB = 0.f;
#pragma unroll
        for (int j = 0; j < 8; j++) {
            S[j][0] = __expf(S[j][0] - mnA);
            S[j][1] = __expf(S[j][1] - mnA);
            S[j][2] = __expf(S[j][2] - mnB);
            S[j][3] = __expf(S[j][3] - mnB);
            sA += S[j][0] + S[j][1];
            sB += S[j][2] + S[j][3];
        }
        sA += __shfl_xor_sync(0xffffffffu, sA, 1);
        sA += __shfl_xor_sync(0xffffffffu, sA, 2);
        sB += __shfl_xor_sync(0xffffffffu, sB, 1);
        sB += __shfl_xor_sync(0xffffffffu, sB, 2);
        lA = lA * cA + sA;  mA = mnA;
        lB = lB * cB + sB;  mB = mnB;
#pragma unroll
        for (int j = 0; j < 8; j++) {
            O[j][0] *= cA; O[j][1] *= cA;
            O[j][2] *= cB; O[j][3] *= cB;
        }

#pragma unroll
        for (int kk = 0; kk < 4; kk++) {
            uint32_t ph[4], pl[4];
#pragma unroll
            for (int u = 0; u < 2; u++) {
                const float* sp = S[2 * kk + u];
#pragma unroll
                for (int hf = 0; hf < 2; hf++) {
                    uint32_t hh, ll;
                    split2(sp[2 * hf], sp[2 * hf + 1], hh, ll);
                    ph[2 * u + hf] = hh;
                    pl[2 * u + hf] = ll;
                }
            }
#pragma unroll
            for (int dimc = 0; dimc < 4; dimc++) {
                uint32_t vh[4], vl[4];
                ldsm4t(vh, sb + AV_HI + v_off + (uint32_t)(kk * 16) * ASTR + dimc * 32);
                ldsm4t(vl, sb + AV_LO + v_off + (uint32_t)(kk * 16) * ASTR + dimc * 32);
                mma16816(O[2 * dimc],     pl, &vh[0]);
                mma16816(O[2 * dimc],     ph, &vl[0]);
                mma16816(O[2 * dimc],     ph, &vh[0]);
                mma16816(O[2 * dimc + 1], pl, &vh[2]);
                mma16816(O[2 * dimc + 1], ph, &vl[2]);
                mma16816(O[2 * dimc + 1], ph, &vh[2]);
            }
        }

        __syncthreads();
        if (more) {
#pragma unroll
            for (int i = 0; i < 4; i++) {
                uint32_t o = (uint32_t)(kr0 + 16 * i) * ASTR + c4 * 8;
                cvt_store8(sm + AK_HI, sm + AK_LO, o, kreg[i]);
                cvt_store8(sm + AV_HI, sm + AV_LO, o, vreg[i]);
            }
            __syncthreads();
        }
    }

    const float invA = 1.f / lA, invB = 1.f / lB;
    const size_t rowA = (size_t)b * SS + qt * 128 + w * 16 + (lane >> 2);
    float* oA = out + rowA * EE + h * 64 + (lane & 3) * 2;
    float* oB = oA + (size_t)8 * EE;
#pragma unroll
    for (int j = 0; j < 8; j++) {
        *(float2*)(oA + j * 8) = make_float2(O[j][0] * invA, O[j][1] * invA);
        *(float2*)(oB + j * 8) = make_float2(O[j][2] * invB, O[j][3] * invB);
    }
}

// ---------------------------------------------------------------------------
// LayerNorm (unchanged)
// ---------------------------------------------------------------------------
__global__ __launch_bounds__(256)
void ln_kernel(const float* __restrict__ r, const float* __restrict__ g,
               const float* __restrict__ be, float* __restrict__ out)
{
    const int row = blockIdx.x;
    const int tid = threadIdx.x;
    const int lane = tid & 31, warp = tid >> 5;

    float4 v = ((const float4*)(r + (size_t)row * EE))[tid];
    float s  = v.x + v.y + v.z + v.w;
    float sq = v.x * v.x + v.y * v.y + v.z * v.z + v.w * v.w;
#pragma unroll
    for (int o = 16; o; o >>= 1) {
        s  += __shfl_xor_sync(0xffffffffu, s,  o);
        sq += __shfl_xor_sync(0xffffffffu, sq, o);
    }
    __shared__ float ss[8], ssq[8];
    if (lane == 0) { ss[warp] = s; ssq[warp] = sq; }
    __syncthreads();
    float ts = 0.f, tq = 0.f;
#pragma unroll
    for (int i = 0; i < 8; i++) { ts += ss[i]; tq += ssq[i]; }
    float mu   = ts * (1.0f / EE);
    float var  = tq * (1.0f / EE) - mu * mu;
    float rstd = rsqrtf(var + 1e-5f);

    float4 gv = ((const float4*)g)[tid];
    float4 bv = ((const float4*)be)[tid];
    float4 o;
    o.x = (v.x - mu) * rstd * gv.x + bv.x;
    o.y = (v.y - mu) * rstd * gv.y + bv.y;
    o.z = (v.z - mu) * rstd * gv.z + bv.z;
    o.w = (v.w - mu) * rstd * gv.w + bv.w;
    ((float4*)(out + (size_t)row * EE))[tid] = o;
}

// ---------------------------------------------------------------------------
// Launch
// ---------------------------------------------------------------------------
extern "C" void kernel_launch(void* const* d_in, const int* in_sizes, int n_in,
                              void* d_out, int out_size)
{
    (void)in_sizes; (void)n_in; (void)out_size;
    const float* x     = (const float*)d_in[0];
    const float* w_qkv = (const float*)d_in[1];
    const float* b_qkv = (const float*)d_in[2];
    const float* w_out = (const float*)d_in[3];
    const float* b_out = (const float*)d_in[4];
    const float* w1    = (const float*)d_in[5];
    const float* b1    = (const float*)d_in[6];
    const float* w2    = (const float*)d_in[7];
    const float* b2    = (const float*)d_in[8];
    const float* g1    = (const float*)d_in[9];
    const float* be1   = (const float*)d_in[10];
    const float* g2    = (const float*)d_in[11];
    const float* be2   = (const float*)d_in[12];
    float* out = (float*)d_out;

    float *p_qkv, *p_att, *p_r1, *p_x1, *p_h, *p_r2;
    cudaGetSymbolAddress((void**)&p_qkv, g_qkv);
    cudaGetSymbolAddress((void**)&p_att, g_att);
    cudaGetSymbolAddress((void**)&p_r1,  g_r1);
    cudaGetSymbolAddress((void**)&p_x1,  g_x1);
    cudaGetSymbolAddress((void**)&p_h,   g_h);
    cudaGetSymbolAddress((void**)&p_r2,  g_r2);

    cudaFuncSetAttribute(attn_mma, cudaFuncAttributeMaxDynamicSharedMemorySize, ATT_SMEM);
    cudaFuncSetAttribute(gemm_mma<false, false>, cudaFuncAttributeMaxDynamicSharedMemorySize, GSM_TOTAL);
    cudaFuncSetAttribute(gemm_mma<false, true>,  cudaFuncAttributeMaxDynamicSharedMemorySize, GSM_TOTAL);
    cudaFuncSetAttribute(gemm_mma<true,  false>, cudaFuncAttributeMaxDynamicSharedMemorySize, GSM_TOTAL);

    // 1) QKV projection
    gemm_mma<false, false><<<dim3(3 * EE / 128, MR / 128), 256, GSM_TOTAL>>>(
        x, w_qkv, b_qkv, nullptr, p_qkv, 3 * EE, EE);

    // 2) attention
    attn_mma<<<dim3(SS / 128, BB * HHN), 256, ATT_SMEM>>>(p_qkv, p_att);

    // 3) out-proj + residual(x)
    gemm_mma<false, true><<<dim3(EE / 128, MR / 128), 256, GSM_TOTAL>>>(
        p_att, w_out, b_out, x, p_r1, EE, EE);

    // 4) LN1
    ln_kernel<<<MR, 256>>>(p_r1, g1, be1, p_x1);

    // 5) FFN up + ReLU
    gemm_mma<true, false><<<dim3(FFD / 128, MR / 128), 256, GSM_TOTAL>>>(
        p_x1, w1, b1, nullptr, p_h, FFD, EE);

    // 6) FFN down + residual(x1)
    gemm_mma<false, true><<<dim3(EE / 128, MR / 128), 256, GSM_TOTAL>>>(
        p_h, w2, b2, p_x1, p_r2, EE, FFD);

    // 7) LN2
    ln_kernel<<<MR, 256>>>(p_r2, g2, be2, out);
}

// round 12
// speedup vs baseline: 1.5428x; 1.0766x over previous
#include <cuda_runtime.h>
#include <cuda_bf16.h>
#include <cuda_fp16.h>
#include <cstdint>
#include <math.h>

// Problem constants
#define BB   4
#define SS   2048
#define EE   1024
#define HHN  16
#define DKH  64
#define FFD  4096
#define MR   (BB*SS)   /* 8192 rows */

// ---------------------------------------------------------------------------
// Scratch
// ---------------------------------------------------------------------------
__device__ float g_qkv[(size_t)MR * 3 * EE];   // 96 MB
__device__ float g_att[(size_t)MR * EE];       // 32 MB
__device__ float g_r1 [(size_t)MR * EE];       // 32 MB
__device__ float g_x1 [(size_t)MR * EE];       // 32 MB
__device__ float g_h  [(size_t)MR * FFD];      // 128 MB
__device__ float g_r2 [(size_t)MR * EE];       // 32 MB

// ---------------------------------------------------------------------------
// Helpers
// ---------------------------------------------------------------------------
__device__ __forceinline__ uint32_t smem_u32(const void* p) {
    uint32_t a;
    asm("{ .reg .u64 t; cvta.to.shared.u64 t, %1; cvt.u32.u64 %0, t; }"
        : "=r"(a) : "l"(p));
    return a;
}

// fp16 mma
__device__ __forceinline__ void mma16816h(float* c, const uint32_t* a, const uint32_t* b) {
    asm volatile(
        "mma.sync.aligned.m16n8k16.row.col.f32.f16.f16.f32 "
        "{%0,%1,%2,%3}, {%4,%5,%6,%7}, {%8,%9}, {%0,%1,%2,%3};"
        : "+f"(c[0]), "+f"(c[1]), "+f"(c[2]), "+f"(c[3])
        : "r"(a[0]), "r"(a[1]), "r"(a[2]), "r"(a[3]), "r"(b[0]), "r"(b[1]));
}

__device__ __forceinline__ void ldsm4(uint32_t* r, uint32_t addr) {
    asm volatile("ldmatrix.sync.aligned.m8n8.x4.shared.b16 {%0,%1,%2,%3}, [%4];"
        : "=r"(r[0]), "=r"(r[1]), "=r"(r[2]), "=r"(r[3]) : "r"(addr));
}

__device__ __forceinline__ void ldsm4t(uint32_t* r, uint32_t addr) {
    asm volatile("ldmatrix.sync.aligned.m8n8.x4.trans.shared.b16 {%0,%1,%2,%3}, [%4];"
        : "=r"(r[0]), "=r"(r[1]), "=r"(r[2]), "=r"(r[3]) : "r"(addr));
}

// fp16 exact split of a float pair -> hi/lo packed half2 words
__device__ __forceinline__ void splith2(float a, float b, uint32_t& hh, uint32_t& ll) {
    __half2 h = __floats2half2_rn(a, b);
    float2 f = __half22float2(h);
    __half2 l = __floats2half2_rn(a - f.x, b - f.y);
    hh = *(uint32_t*)&h;
    ll = *(uint32_t*)&l;
}

// fp16 exact 2-term split of 4 floats -> hi/lo tiles
__device__ __forceinline__ void cvt_store8_f16split(char* hi, char* lo, uint32_t boff, float4 v) {
    uint32_t h0, h1, l0, l1;
    splith2(v.x, v.y, h0, l0);
    splith2(v.z, v.w, h1, l1);
    *(uint2*)(hi + boff) = make_uint2(h0, h1);
    *(uint2*)(lo + boff) = make_uint2(l0, l1);
}

// fp16 single rounding of 4 floats -> one tile
__device__ __forceinline__ void cvt_store8_f16(char* dst, uint32_t boff, float4 v) {
    __half2 h0 = __floats2half2_rn(v.x, v.y);
    __half2 h1 = __floats2half2_rn(v.z, v.w);
    *(uint2*)(dst + boff) = make_uint2(*(uint32_t*)&h0, *(uint32_t*)&h1);
}

// ---------------------------------------------------------------------------
// GEMM via mma.sync fp16 2-pass: C = (Ah+Al) @ f16(W)^T (R11-identical)
// ---------------------------------------------------------------------------
#define SBYTE 80
#define TILE_A_HI 0
#define TILE_A_LO 10240
#define TILE_B    20480
#define STAGE     30720
#define GSM_TOTAL (2 * STAGE)

template<bool RELU, bool RES>
__global__ __launch_bounds__(256, 1)
void gemm_mma(const float* __restrict__ A, const float* __restrict__ W,
              const float* __restrict__ bias, const float* __restrict__ res,
              float* __restrict__ C, int N, int K)
{
    extern __shared__ char sm[];
    const int tid = threadIdx.x, lane = tid & 31, wid = tid >> 5;
    const int wm = wid & 1;
    const int wn = wid >> 1;
    const int bm = blockIdx.y * 128, bn = blockIdx.x * 128;
    const uint32_t sbase = smem_u32(sm);

    const uint32_t a_off = (uint32_t)(wm * 64 + (lane & 15)) * SBYTE + ((lane >> 4) * 16);
    const uint32_t b_off = (uint32_t)(wn * 32 + (lane & 7) + ((lane >> 4) << 3)) * SBYTE
                         + (((lane >> 3) & 1) * 16);

    const int c4 = tid & 7, r0 = tid >> 3;
    const float* Ap = A + (size_t)(bm + r0) * K + c4 * 4;
    const float* Wp = W + (size_t)(bn + r0) * K + c4 * 4;
    const uint32_t st_off = (uint32_t)r0 * SBYTE + c4 * 8;

    float acc[4][4][4];
#pragma unroll
    for (int mt = 0; mt < 4; mt++)
#pragma unroll
        for (int nt = 0; nt < 4; nt++)
#pragma unroll
            for (int j = 0; j < 4; j++) acc[mt][nt][j] = 0.f;

    float4 va[4], vb[4];
#pragma unroll
    for (int i = 0; i < 4; i++) {
        va[i] = *(const float4*)(Ap + (size_t)(32 * i) * K);
        vb[i] = *(const float4*)(Wp + (size_t)(32 * i) * K);
    }
#pragma unroll
    for (int i = 0; i < 4; i++) {
        uint32_t o = st_off + i * 32 * SBYTE;
        cvt_store8_f16split(sm + TILE_A_HI, sm + TILE_A_LO, o, va[i]);
        cvt_store8_f16(sm + TILE_B, o, vb[i]);
    }
    __syncthreads();

    const int KT = K >> 5;
    for (int kt = 0; kt < KT; kt++) {
        if (kt + 1 < KT) {
#pragma unroll
            for (int i = 0; i < 4; i++) {
                va[i] = *(const float4*)(Ap + (size_t)(32 * i) * K + (kt + 1) * 32);
                vb[i] = *(const float4*)(Wp + (size_t)(32 * i) * K + (kt + 1) * 32);
            }
        }
        const uint32_t base = sbase + (kt & 1) * STAGE;
#pragma unroll
        for (int ks = 0; ks < 2; ks++) {
            uint32_t ah[4][4], al[4][4], bh[2][4];
#pragma unroll
            for (int t = 0; t < 4; t++) {
                ldsm4(ah[t], base + TILE_A_HI + a_off + t * (16 * SBYTE) + ks * 32);
                ldsm4(al[t], base + TILE_A_LO + a_off + t * (16 * SBYTE) + ks * 32);
            }
#pragma unroll
            for (int i = 0; i < 2; i++)
                ldsm4(bh[i], base + TILE_B + b_off + i * (16 * SBYTE) + ks * 32);
#pragma unroll
            for (int mt = 0; mt < 4; mt++)
#pragma unroll
                for (int nt = 0; nt < 4; nt++) {
                    const uint32_t* bph = &bh[nt >> 1][(nt & 1) * 2];
                    mma16816h(acc[mt][nt], al[mt], bph);
                    mma16816h(acc[mt][nt], ah[mt], bph);
                }
        }
        if (kt + 1 < KT) {
            char* nb = sm + ((kt + 1) & 1) * STAGE;
#pragma unroll
            for (int i = 0; i < 4; i++) {
                uint32_t o = st_off + i * 32 * SBYTE;
                cvt_store8_f16split(nb + TILE_A_HI, nb + TILE_A_LO, o, va[i]);
                cvt_store8_f16(nb + TILE_B, o, vb[i]);
            }
        }
        __syncthreads();
    }

    const int erow = bm + wm * 64 + (lane >> 2);
    const int ecol = bn + wn * 32 + (lane & 3) * 2;
#pragma unroll
    for (int mt = 0; mt < 4; mt++)
#pragma unroll
        for (int nt = 0; nt < 4; nt++) {
            const int col = ecol + nt * 8;
            float2 bv = *(const float2*)(bias + col);
#pragma unroll
            for (int h2 = 0; h2 < 2; h2++) {
                const int row = erow + mt * 16 + h2 * 8;
                float o0 = acc[mt][nt][h2 * 2 + 0] + bv.x;
                float o1 = acc[mt][nt][h2 * 2 + 1] + bv.y;
                if (RES) {
                    float2 rv = *(const float2*)(res + (size_t)row * N + col);
                    o0 += rv.x; o1 += rv.y;
                }
                if (RELU) { o0 = fmaxf(o0, 0.f); o1 = fmaxf(o1, 0.f); }
                *(float2*)(C + (size_t)row * N + col) = make_float2(o0, o1);
            }
        }
}

// ---------------------------------------------------------------------------
// Flash attention via mma.sync, fp16 2-pass:
//   S = (Qh+Ql)·f16(K)^T ; O += (Ph+Pl)·f16(V)
// CTA = (b,h,128-query block), 8 warps x 16 rows, 64-key tiles.
// ---------------------------------------------------------------------------
#define ASTR   144
#define AQ_HI  0
#define AQ_LO  (128 * ASTR)
#define AK     (2 * 128 * ASTR)
#define AV     (AK + 64 * ASTR)
#define ATT_SMEM (AV + 64 * ASTR)   /* 55296 */

__global__ __launch_bounds__(256, 1)
void attn_mma(const float* __restrict__ qkv, float* __restrict__ out)
{
    extern __shared__ char sm[];
    const uint32_t sb = smem_u32(sm);
    const int tid = threadIdx.x, lane = tid & 31, w = tid >> 5;
    const int qt = blockIdx.x;
    const int bh = blockIdx.y;
    const int b = bh >> 4, h = bh & 15;

    const float* base = qkv + (size_t)b * SS * (3 * EE);

    // Q tile [128x64], scaled 1/8, exact fp16 split
    {
        const int c4q = tid & 15, r0q = tid >> 4;
#pragma unroll
        for (int i = 0; i < 8; i++) {
            int r = r0q + 16 * i;
            float4 v = *(const float4*)(base + (size_t)(qt * 128 + r) * (3 * EE) + h * 64 + c4q * 4);
            v.x *= 0.125f; v.y *= 0.125f; v.z *= 0.125f; v.w *= 0.125f;
            cvt_store8_f16split(sm + AQ_HI, sm + AQ_LO, (uint32_t)r * ASTR + c4q * 8, v);
        }
    }

    const int c4 = tid & 15, kr0 = tid >> 4;
    const float* kbase = base + EE + h * 64 + c4 * 4;
    const float* vbase = kbase + EE;

    float4 kreg[4], vreg[4];
#pragma unroll
    for (int i = 0; i < 4; i++) {
        kreg[i] = *(const float4*)(kbase + (size_t)(kr0 + 16 * i) * (3 * EE));
        vreg[i] = *(const float4*)(vbase + (size_t)(kr0 + 16 * i) * (3 * EE));
    }
#pragma unroll
    for (int i = 0; i < 4; i++) {
        uint32_t o = (uint32_t)(kr0 + 16 * i) * ASTR + c4 * 8;
        cvt_store8_f16(sm + AK, o, kreg[i]);
        cvt_store8_f16(sm + AV, o, vreg[i]);
    }
    __syncthreads();

    const uint32_t a_off = (uint32_t)(w * 16 + (lane & 15)) * ASTR + ((lane >> 4) * 16);
    const uint32_t b_off = (uint32_t)((lane & 7) + ((lane >> 4) << 3)) * ASTR
                         + (((lane >> 3) & 1) * 16);
    const uint32_t v_off = (uint32_t)(lane & 15) * ASTR + ((lane >> 4) * 16);

    float mA = -1e30f, mB = -1e30f, lA = 0.f, lB = 0.f;
    float O[8][4];
#pragma unroll
    for (int j = 0; j < 8; j++)
#pragma unroll
        for (int k = 0; k < 4; k++) O[j][k] = 0.f;

    const int NT = SS / 64;
    for (int kt = 0; kt < NT; kt++) {
        const bool more = (kt + 1 < NT);
        if (more) {
#pragma unroll
            for (int i = 0; i < 4; i++) {
                kreg[i] = *(const float4*)(kbase + (size_t)((kt + 1) * 64 + kr0 + 16 * i) * (3 * EE));
                vreg[i] = *(const float4*)(vbase + (size_t)((kt + 1) * 64 + kr0 + 16 * i) * (3 * EE));
            }
        }

        // ---- S = Q K^T (2-pass fp16) ----
        float S[8][4];
#pragma unroll
        for (int j = 0; j < 8; j++)
#pragma unroll
            for (int k = 0; k < 4; k++) S[j][k] = 0.f;

#pragma unroll
        for (int kd = 0; kd < 4; kd++) {
            uint32_t ah[4], al[4];
            ldsm4(ah, sb + AQ_HI + a_off + kd * 32);
            ldsm4(al, sb + AQ_LO + a_off + kd * 32);
#pragma unroll
            for (int i = 0; i < 4; i++) {
                uint32_t bh4[4];
                ldsm4(bh4, sb + AK + b_off + i * (16 * ASTR) + kd * 32);
                mma16816h(S[2 * i],     al, &bh4[0]);
                mma16816h(S[2 * i],     ah, &bh4[0]);
                mma16816h(S[2 * i + 1], al, &bh4[2]);
                mma16816h(S[2 * i + 1], ah, &bh4[2]);
            }
        }

        // ---- online softmax ----
        float txA = -1e30f, txB = -1e30f;
#pragma unroll
        for (int j = 0; j < 8; j++) {
            txA = fmaxf(txA, fmaxf(S[j][0], S[j][1]));
            txB = fmaxf(txB, fmaxf(S[j][2], S[j][3]));
        }
        txA = fmaxf(txA, __shfl_xor_sync(0xffffffffu, txA, 1));
        txA = fmaxf(txA, __shfl_xor_sync(0xffffffffu, txA, 2));
        txB = fmaxf(txB, __shfl_xor_sync(0xffffffffu, txB, 1));
        txB = fmaxf(txB, __shfl_xor_sync(0xffffffffu, txB, 2));
        const float mnA = fmaxf(mA, txA), mnB = fmaxf(mB, txB);
        const float cA = __expf(mA - mnA), cB = __expf(mB - mnB);

        float sA = 0.f, sB = 0.f;
#pragma unroll
        for (int j = 0; j < 8; j++) {
            S[j][0] = __expf(S[j][0] - mnA);
            S[j][1] = __expf(S[j][1] - mnA);
            S[j][2] = __expf(S[j][2] - mnB);
            S[j][3] = __expf(S[j][3] - mnB);
            sA += S[j][0] + S[j][1];
            sB += S[j][2] + S[j][3];
        }
        sA += __shfl_xor_sync(0xffffffffu, sA, 1);
        sA += __shfl_xor_sync(0xffffffffu, sA, 2);
        sB += __shfl_xor_sync(0xffffffffu, sB, 1);
        sB += __shfl_xor_sync(0xffffffffu, sB, 2);
        lA = lA * cA + sA;  mA = mnA;
        lB = lB * cB + sB;  mB = mnB;
#pragma unroll
        for (int j = 0; j < 8; j++) {
            O[j][0] *= cA; O[j][1] *= cA;
            O[j][2] *= cB; O[j][3] *= cB;
        }

        // ---- O += P V (2-pass fp16: P split, V rounded) ----
#pragma unroll
        for (int kk = 0; kk < 4; kk++) {
            uint32_t ph[4], pl[4];
#pragma unroll
            for (int u = 0; u < 2; u++) {
                const float* sp = S[2 * kk + u];
#pragma unroll
                for (int hf = 0; hf < 2; hf++) {
                    uint32_t hh, ll;
                    splith2(sp[2 * hf], sp[2 * hf + 1], hh, ll);
                    ph[2 * u + hf] = hh;
                    pl[2 * u + hf] = ll;
                }
            }
#pragma unroll
            for (int dimc = 0; dimc < 4; dimc++) {
                uint32_t vh[4];
                ldsm4t(vh, sb + AV + v_off + (uint32_t)(kk * 16) * ASTR + dimc * 32);
                mma16816h(O[2 * dimc],     pl, &vh[0]);
                mma16816h(O[2 * dimc],     ph, &vh[0]);
                mma16816h(O[2 * dimc + 1], pl, &vh[2]);
                mma16816h(O[2 * dimc + 1], ph, &vh[2]);
            }
        }

        __syncthreads();
        if (more) {
#pragma unroll
            for (int i = 0; i < 4; i++) {
                uint32_t o = (uint32_t)(kr0 + 16 * i) * ASTR + c4 * 8;
                cvt_store8_f16(sm + AK, o, kreg[i]);
                cvt_store8_f16(sm + AV, o, vreg[i]);
            }
            __syncthreads();
        }
    }

    const float invA = 1.f / lA, invB = 1.f / lB;
    const size_t rowA = (size_t)b * SS + qt * 128 + w * 16 + (lane >> 2);
    float* oA = out + rowA * EE + h * 64 + (lane & 3) * 2;
    float* oB = oA + (size_t)8 * EE;
#pragma unroll
    for (int j = 0; j < 8; j++) {
        *(float2*)(oA + j * 8) = make_float2(O[j][0] * invA, O[j][1] * invA);
        *(float2*)(oB + j * 8) = make_float2(O[j][2] * invB, O[j][3] * invB);
    }
}

// ---------------------------------------------------------------------------
// LayerNorm (unchanged)
// ---------------------------------------------------------------------------
__global__ __launch_bounds__(256)
void ln_kernel(const float* __restrict__ r, const float* __restrict__ g,
               const float* __restrict__ be, float* __restrict__ out)
{
    const int row = blockIdx.x;
    const int tid = threadIdx.x;
    const int lane = tid & 31, warp = tid >> 5;

    float4 v = ((const float4*)(r + (size_t)row * EE))[tid];
    float s  = v.x + v.y + v.z + v.w;
    float sq = v.x * v.x + v.y * v.y + v.z * v.z + v.w * v.w;
#pragma unroll
    for (int o = 16; o; o >>= 1) {
        s  += __shfl_xor_sync(0xffffffffu, s,  o);
        sq += __shfl_xor_sync(0xffffffffu, sq, o);
    }
    __shared__ float ss[8], ssq[8];
    if (lane == 0) { ss[warp] = s; ssq[warp] = sq; }
    __syncthreads();
    float ts = 0.f, tq = 0.f;
#pragma unroll
    for (int i = 0; i < 8; i++) { ts += ss[i]; tq += ssq[i]; }
    float mu   = ts * (1.0f / EE);
    float var  = tq * (1.0f / EE) - mu * mu;
    float rstd = rsqrtf(var + 1e-5f);

    float4 gv = ((const float4*)g)[tid];
    float4 bv = ((const float4*)be)[tid];
    float4 o;
    o.x = (v.x - mu) * rstd * gv.x + bv.x;
    o.y = (v.y - mu) * rstd * gv.y + bv.y;
    o.z = (v.z - mu) * rstd * gv.z + bv.z;
    o.w = (v.w - mu) * rstd * gv.w + bv.w;
    ((float4*)(out + (size_t)row * EE))[tid] = o;
}

// ---------------------------------------------------------------------------
// Launch
// ---------------------------------------------------------------------------
extern "C" void kernel_launch(void* const* d_in, const int* in_sizes, int n_in,
                              void* d_out, int out_size)
{
    (void)in_sizes; (void)n_in; (void)out_size;
    const float* x     = (const float*)d_in[0];
    const float* w_qkv = (const float*)d_in[1];
    const float* b_qkv = (const float*)d_in[2];
    const float* w_out = (const float*)d_in[3];
    const float* b_out = (const float*)d_in[4];
    const float* w1    = (const float*)d_in[5];
    const float* b1    = (const float*)d_in[6];
    const float* w2    = (const float*)d_in[7];
    const float* b2    = (const float*)d_in[8];
    const float* g1    = (const float*)d_in[9];
    const float* be1   = (const float*)d_in[10];
    const float* g2    = (const float*)d_in[11];
    const float* be2   = (const float*)d_in[12];
    float* out = (float*)d_out;

    float *p_qkv, *p_att, *p_r1, *p_x1, *p_h, *p_r2;
    cudaGetSymbolAddress((void**)&p_qkv, g_qkv);
    cudaGetSymbolAddress((void**)&p_att, g_att);
    cudaGetSymbolAddress((void**)&p_r1,  g_r1);
    cudaGetSymbolAddress((void**)&p_x1,  g_x1);
    cudaGetSymbolAddress((void**)&p_h,   g_h);
    cudaGetSymbolAddress((void**)&p_r2,  g_r2);

    cudaFuncSetAttribute(attn_mma, cudaFuncAttributeMaxDynamicSharedMemorySize, ATT_SMEM);
    cudaFuncSetAttribute(gemm_mma<false, false>, cudaFuncAttributeMaxDynamicSharedMemorySize, GSM_TOTAL);
    cudaFuncSetAttribute(gemm_mma<false, true>,  cudaFuncAttributeMaxDynamicSharedMemorySize, GSM_TOTAL);
    cudaFuncSetAttribute(gemm_mma<true,  false>, cudaFuncAttributeMaxDynamicSharedMemorySize, GSM_TOTAL);

    // 1) QKV projection
    gemm_mma<false, false><<<dim3(3 * EE / 128, MR / 128), 256, GSM_TOTAL>>>(
        x, w_qkv, b_qkv, nullptr, p_qkv, 3 * EE, EE);

    // 2) attention
    attn_mma<<<dim3(SS / 128, BB * HHN), 256, ATT_SMEM>>>(p_qkv, p_att);

    // 3) out-proj + residual(x)
    gemm_mma<false, true><<<dim3(EE / 128, MR / 128), 256, GSM_TOTAL>>>(
        p_att, w_out, b_out, x, p_r1, EE, EE);

    // 4) LN1
    ln_kernel<<<MR, 256>>>(p_r1, g1, be1, p_x1);

    // 5) FFN up + ReLU
    gemm_mma<true, false><<<dim3(FFD / 128, MR / 128), 256, GSM_TOTAL>>>(
        p_x1, w1, b1, nullptr, p_h, FFD, EE);

    // 6) FFN down + residual(x1)
    gemm_mma<false, true><<<dim3(EE / 128, MR / 128), 256, GSM_TOTAL>>>(
        p_h, w2, b2, p_x1, p_r2, EE, FFD);

    // 7) LN2
    ln_kernel<<<MR, 256>>>(p_r2, g2, be2, out);
}

// round 13
// speedup vs baseline: 1.7894x; 1.1599x over previous
#include <cuda_runtime.h>
#include <cuda_bf16.h>
#include <cuda_fp16.h>
#include <cstdint>
#include <math.h>

// Problem constants
#define BB   4
#define SS   2048
#define EE   1024
#define HHN  16
#define DKH  64
#define FFD  4096
#define MR   (BB*SS)   /* 8192 rows */

// ---------------------------------------------------------------------------
// Scratch
// ---------------------------------------------------------------------------
__device__ float g_qkv[(size_t)MR * 3 * EE];   // 96 MB
__device__ float g_att[(size_t)MR * EE];       // 32 MB
__device__ float g_r1 [(size_t)MR * EE];       // 32 MB
__device__ float g_x1 [(size_t)MR * EE];       // 32 MB
__device__ float g_h  [(size_t)MR * FFD];      // 128 MB
__device__ float g_r2 [(size_t)MR * EE];       // 32 MB

// ---------------------------------------------------------------------------
// Helpers
// ---------------------------------------------------------------------------
__device__ __forceinline__ uint32_t smem_u32(const void* p) {
    uint32_t a;
    asm("{ .reg .u64 t; cvta.to.shared.u64 t, %1; cvt.u32.u64 %0, t; }"
        : "=r"(a) : "l"(p));
    return a;
}

// fp16 mma
__device__ __forceinline__ void mma16816h(float* c, const uint32_t* a, const uint32_t* b) {
    asm volatile(
        "mma.sync.aligned.m16n8k16.row.col.f32.f16.f16.f32 "
        "{%0,%1,%2,%3}, {%4,%5,%6,%7}, {%8,%9}, {%0,%1,%2,%3};"
        : "+f"(c[0]), "+f"(c[1]), "+f"(c[2]), "+f"(c[3])
        : "r"(a[0]), "r"(a[1]), "r"(a[2]), "r"(a[3]), "r"(b[0]), "r"(b[1]));
}

__device__ __forceinline__ void ldsm4(uint32_t* r, uint32_t addr) {
    asm volatile("ldmatrix.sync.aligned.m8n8.x4.shared.b16 {%0,%1,%2,%3}, [%4];"
        : "=r"(r[0]), "=r"(r[1]), "=r"(r[2]), "=r"(r[3]) : "r"(addr));
}

__device__ __forceinline__ void ldsm4t(uint32_t* r, uint32_t addr) {
    asm volatile("ldmatrix.sync.aligned.m8n8.x4.trans.shared.b16 {%0,%1,%2,%3}, [%4];"
        : "=r"(r[0]), "=r"(r[1]), "=r"(r[2]), "=r"(r[3]) : "r"(addr));
}

// fp16 single rounding of 4 floats -> one tile
__device__ __forceinline__ void cvt_store8_f16(char* dst, uint32_t boff, float4 v) {
    __half2 h0 = __floats2half2_rn(v.x, v.y);
    __half2 h1 = __floats2half2_rn(v.z, v.w);
    *(uint2*)(dst + boff) = make_uint2(*(uint32_t*)&h0, *(uint32_t*)&h1);
}

// ---------------------------------------------------------------------------
// GEMM via mma.sync fp16 single-pass: C = f16(A) @ f16(W)^T (+bias,res,relu)
// CTA tile 128x128, BK=32, 256 thr (2M x 4N warps), double-buffered.
// ---------------------------------------------------------------------------
#define SBYTE 80
#define TILE_A 0
#define TILE_B 10240
#define STAGE  20480
#define GSM_TOTAL (2 * STAGE)

template<bool RELU, bool RES>
__global__ __launch_bounds__(256, 1)
void gemm_mma(const float* __restrict__ A, const float* __restrict__ W,
              const float* __restrict__ bias, const float* __restrict__ res,
              float* __restrict__ C, int N, int K)
{
    extern __shared__ char sm[];
    const int tid = threadIdx.x, lane = tid & 31, wid = tid >> 5;
    const int wm = wid & 1;
    const int wn = wid >> 1;
    const int bm = blockIdx.y * 128, bn = blockIdx.x * 128;
    const uint32_t sbase = smem_u32(sm);

    const uint32_t a_off = (uint32_t)(wm * 64 + (lane & 15)) * SBYTE + ((lane >> 4) * 16);
    const uint32_t b_off = (uint32_t)(wn * 32 + (lane & 7) + ((lane >> 4) << 3)) * SBYTE
                         + (((lane >> 3) & 1) * 16);

    const int c4 = tid & 7, r0 = tid >> 3;
    const float* Ap = A + (size_t)(bm + r0) * K + c4 * 4;
    const float* Wp = W + (size_t)(bn + r0) * K + c4 * 4;
    const uint32_t st_off = (uint32_t)r0 * SBYTE + c4 * 8;

    float acc[4][4][4];
#pragma unroll
    for (int mt = 0; mt < 4; mt++)
#pragma unroll
        for (int nt = 0; nt < 4; nt++)
#pragma unroll
            for (int j = 0; j < 4; j++) acc[mt][nt][j] = 0.f;

    float4 va[4], vb[4];
#pragma unroll
    for (int i = 0; i < 4; i++) {
        va[i] = *(const float4*)(Ap + (size_t)(32 * i) * K);
        vb[i] = *(const float4*)(Wp + (size_t)(32 * i) * K);
    }
#pragma unroll
    for (int i = 0; i < 4; i++) {
        uint32_t o = st_off + i * 32 * SBYTE;
        cvt_store8_f16(sm + TILE_A, o, va[i]);
        cvt_store8_f16(sm + TILE_B, o, vb[i]);
    }
    __syncthreads();

    const int KT = K >> 5;
    for (int kt = 0; kt < KT; kt++) {
        if (kt + 1 < KT) {
#pragma unroll
            for (int i = 0; i < 4; i++) {
                va[i] = *(const float4*)(Ap + (size_t)(32 * i) * K + (kt + 1) * 32);
                vb[i] = *(const float4*)(Wp + (size_t)(32 * i) * K + (kt + 1) * 32);
            }
        }
        const uint32_t base = sbase + (kt & 1) * STAGE;
#pragma unroll
        for (int ks = 0; ks < 2; ks++) {
            uint32_t ah[4][4], bh[2][4];
#pragma unroll
            for (int t = 0; t < 4; t++)
                ldsm4(ah[t], base + TILE_A + a_off + t * (16 * SBYTE) + ks * 32);
#pragma unroll
            for (int i = 0; i < 2; i++)
                ldsm4(bh[i], base + TILE_B + b_off + i * (16 * SBYTE) + ks * 32);
#pragma unroll
            for (int mt = 0; mt < 4; mt++)
#pragma unroll
                for (int nt = 0; nt < 4; nt++)
                    mma16816h(acc[mt][nt], ah[mt], &bh[nt >> 1][(nt & 1) * 2]);
        }
        if (kt + 1 < KT) {
            char* nb = sm + ((kt + 1) & 1) * STAGE;
#pragma unroll
            for (int i = 0; i < 4; i++) {
                uint32_t o = st_off + i * 32 * SBYTE;
                cvt_store8_f16(nb + TILE_A, o, va[i]);
                cvt_store8_f16(nb + TILE_B, o, vb[i]);
            }
        }
        __syncthreads();
    }

    const int erow = bm + wm * 64 + (lane >> 2);
    const int ecol = bn + wn * 32 + (lane & 3) * 2;
#pragma unroll
    for (int mt = 0; mt < 4; mt++)
#pragma unroll
        for (int nt = 0; nt < 4; nt++) {
            const int col = ecol + nt * 8;
            float2 bv = *(const float2*)(bias + col);
#pragma unroll
            for (int h2 = 0; h2 < 2; h2++) {
                const int row = erow + mt * 16 + h2 * 8;
                float o0 = acc[mt][nt][h2 * 2 + 0] + bv.x;
                float o1 = acc[mt][nt][h2 * 2 + 1] + bv.y;
                if (RES) {
                    float2 rv = *(const float2*)(res + (size_t)row * N + col);
                    o0 += rv.x; o1 += rv.y;
                }
                if (RELU) { o0 = fmaxf(o0, 0.f); o1 = fmaxf(o1, 0.f); }
                *(float2*)(C + (size_t)row * N + col) = make_float2(o0, o1);
            }
        }
}

// ---------------------------------------------------------------------------
// Flash attention via mma.sync, fp16 single-pass:
//   S = f16(Q/8)·f16(K)^T ; O += f16(P)·f16(V)
// CTA = (b,h,128-query block), 8 warps x 16 rows, 64-key tiles.
// ---------------------------------------------------------------------------
#define ASTR   144
#define AQ     0
#define AK     (128 * ASTR)
#define AV     (AK + 64 * ASTR)
#define ATT_SMEM (AV + 64 * ASTR)   /* 36864 */

__global__ __launch_bounds__(256, 1)
void attn_mma(const float* __restrict__ qkv, float* __restrict__ out)
{
    extern __shared__ char sm[];
    const uint32_t sb = smem_u32(sm);
    const int tid = threadIdx.x, lane = tid & 31, w = tid >> 5;
    const int qt = blockIdx.x;
    const int bh = blockIdx.y;
    const int b = bh >> 4, h = bh & 15;

    const float* base = qkv + (size_t)b * SS * (3 * EE);

    // Q tile [128x64], scaled 1/8, single fp16 rounding
    {
        const int c4q = tid & 15, r0q = tid >> 4;
#pragma unroll
        for (int i = 0; i < 8; i++) {
            int r = r0q + 16 * i;
            float4 v = *(const float4*)(base + (size_t)(qt * 128 + r) * (3 * EE) + h * 64 + c4q * 4);
            v.x *= 0.125f; v.y *= 0.125f; v.z *= 0.125f; v.w *= 0.125f;
            cvt_store8_f16(sm + AQ, (uint32_t)r * ASTR + c4q * 8, v);
        }
    }

    const int c4 = tid & 15, kr0 = tid >> 4;
    const float* kbase = base + EE + h * 64 + c4 * 4;
    const float* vbase = kbase + EE;

    float4 kreg[4], vreg[4];
#pragma unroll
    for (int i = 0; i < 4; i++) {
        kreg[i] = *(const float4*)(kbase + (size_t)(kr0 + 16 * i) * (3 * EE));
        vreg[i] = *(const float4*)(vbase + (size_t)(kr0 + 16 * i) * (3 * EE));
    }
#pragma unroll
    for (int i = 0; i < 4; i++) {
        uint32_t o = (uint32_t)(kr0 + 16 * i) * ASTR + c4 * 8;
        cvt_store8_f16(sm + AK, o, kreg[i]);
        cvt_store8_f16(sm + AV, o, vreg[i]);
    }
    __syncthreads();

    const uint32_t a_off = (uint32_t)(w * 16 + (lane & 15)) * ASTR + ((lane >> 4) * 16);
    const uint32_t b_off = (uint32_t)((lane & 7) + ((lane >> 4) << 3)) * ASTR
                         + (((lane >> 3) & 1) * 16);
    const uint32_t v_off = (uint32_t)(lane & 15) * ASTR + ((lane >> 4) * 16);

    float mA = -1e30f, mB = -1e30f, lA = 0.f, lB = 0.f;
    float O[8][4];
#pragma unroll
    for (int j = 0; j < 8; j++)
#pragma unroll
        for (int k = 0; k < 4; k++) O[j][k] = 0.f;

    const int NT = SS / 64;
    for (int kt = 0; kt < NT; kt++) {
        const bool more = (kt + 1 < NT);
        if (more) {
#pragma unroll
            for (int i = 0; i < 4; i++) {
                kreg[i] = *(const float4*)(kbase + (size_t)((kt + 1) * 64 + kr0 + 16 * i) * (3 * EE));
                vreg[i] = *(const float4*)(vbase + (size_t)((kt + 1) * 64 + kr0 + 16 * i) * (3 * EE));
            }
        }

        // ---- S = Q K^T (single-pass fp16) ----
        float S[8][4];
#pragma unroll
        for (int j = 0; j < 8; j++)
#pragma unroll
            for (int k = 0; k < 4; k++) S[j][k] = 0.f;

#pragma unroll
        for (int kd = 0; kd < 4; kd++) {
            uint32_t ah[4];
            ldsm4(ah, sb + AQ + a_off + kd * 32);
#pragma unroll
            for (int i = 0; i < 4; i++) {
                uint32_t bh4[4];
                ldsm4(bh4, sb + AK + b_off + i * (16 * ASTR) + kd * 32);
                mma16816h(S[2 * i],     ah, &bh4[0]);
                mma16816h(S[2 * i + 1], ah, &bh4[2]);
            }
        }

        // ---- online softmax ----
        float txA = -1e30f, txB = -1e30f;
#pragma unroll
        for (int j = 0; j < 8; j++) {
            txA = fmaxf(txA, fmaxf(S[j][0], S[j][1]));
            txB = fmaxf(txB, fmaxf(S[j][2], S[j][3]));
        }
        txA = fmaxf(txA, __shfl_xor_sync(0xffffffffu, txA, 1));
        txA = fmaxf(txA, __shfl_xor_sync(0xffffffffu, txA, 2));
        txB = fmaxf(txB, __shfl_xor_sync(0xffffffffu, txB, 1));
        txB = fmaxf(txB, __shfl_xor_sync(0xffffffffu, txB, 2));
        const float mnA = fmaxf(mA, txA), mnB = fmaxf(mB, txB);
        const float cA = __expf(mA - mnA), cB = __expf(mB - mnB);

        float sA = 0.f, sB = 0.f;
#pragma unroll
        for (int j = 0; j < 8; j++) {
            S[j][0] = __expf(S[j][0] - mnA);
            S[j][1] = __expf(S[j][1] - mnA);
            S[j][2] = __expf(S[j][2] - mnB);
            S[j][3] = __expf(S[j][3] - mnB);
            sA += S[j][0] + S[j][1];
            sB += S[j][2] + S[j][3];
        }
        sA += __shfl_xor_sync(0xffffffffu, sA, 1);
        sA += __shfl_xor_sync(0xffffffffu, sA, 2);
        sB += __shfl_xor_sync(0xffffffffu, sB, 1);
        sB += __shfl_xor_sync(0xffffffffu, sB, 2);
        lA = lA * cA + sA;  mA = mnA;
        lB = lB * cB + sB;  mB = mnB;
#pragma unroll
        for (int j = 0; j < 8; j++) {
            O[j][0] *= cA; O[j][1] *= cA;
            O[j][2] *= cB; O[j][3] *= cB;
        }

        // ---- O += P V (single-pass fp16) ----
#pragma unroll
        for (int kk = 0; kk < 4; kk++) {
            uint32_t ph[4];
#pragma unroll
            for (int u = 0; u < 2; u++) {
                const float* sp = S[2 * kk + u];
                __half2 p0 = __floats2half2_rn(sp[0], sp[1]);
                __half2 p1 = __floats2half2_rn(sp[2], sp[3]);
                ph[2 * u]     = *(uint32_t*)&p0;
                ph[2 * u + 1] = *(uint32_t*)&p1;
            }
#pragma unroll
            for (int dimc = 0; dimc < 4; dimc++) {
                uint32_t vh[4];
                ldsm4t(vh, sb + AV + v_off + (uint32_t)(kk * 16) * ASTR + dimc * 32);
                mma16816h(O[2 * dimc],     ph, &vh[0]);
                mma16816h(O[2 * dimc + 1], ph, &vh[2]);
            }
        }

        __syncthreads();
        if (more) {
#pragma unroll
            for (int i = 0; i < 4; i++) {
                uint32_t o = (uint32_t)(kr0 + 16 * i) * ASTR + c4 * 8;
                cvt_store8_f16(sm + AK, o, kreg[i]);
                cvt_store8_f16(sm + AV, o, vreg[i]);
            }
            __syncthreads();
        }
    }

    const float invA = 1.f / lA, invB = 1.f / lB;
    const size_t rowA = (size_t)b * SS + qt * 128 + w * 16 + (lane >> 2);
    float* oA = out + rowA * EE + h * 64 + (lane & 3) * 2;
    float* oB = oA + (size_t)8 * EE;
#pragma unroll
    for (int j = 0; j < 8; j++) {
        *(float2*)(oA + j * 8) = make_float2(O[j][0] * invA, O[j][1] * invA);
        *(float2*)(oB + j * 8) = make_float2(O[j][2] * invB, O[j][3] * invB);
    }
}

// ---------------------------------------------------------------------------
// LayerNorm (unchanged)
// ---------------------------------------------------------------------------
__global__ __launch_bounds__(256)
void ln_kernel(const float* __restrict__ r, const float* __restrict__ g,
               const float* __restrict__ be, float* __restrict__ out)
{
    const int row = blockIdx.x;
    const int tid = threadIdx.x;
    const int lane = tid & 31, warp = tid >> 5;

    float4 v = ((const float4*)(r + (size_t)row * EE))[tid];
    float s  = v.x + v.y + v.z + v.w;
    float sq = v.x * v.x + v.y * v.y + v.z * v.z + v.w * v.w;
#pragma unroll
    for (int o = 16; o; o >>= 1) {
        s  += __shfl_xor_sync(0xffffffffu, s,  o);
        sq += __shfl_xor_sync(0xffffffffu, sq, o);
    }
    __shared__ float ss[8], ssq[8];
    if (lane == 0) { ss[warp] = s; ssq[warp] = sq; }
    __syncthreads();
    float ts = 0.f, tq = 0.f;
#pragma unroll
    for (int i = 0; i < 8; i++) { ts += ss[i]; tq += ssq[i]; }
    float mu   = ts * (1.0f / EE);
    float var  = tq * (1.0f / EE) - mu * mu;
    float rstd = rsqrtf(var + 1e-5f);

    float4 gv = ((const float4*)g)[tid];
    float4 bv = ((const float4*)be)[tid];
    float4 o;
    o.x = (v.x - mu) * rstd * gv.x + bv.x;
    o.y = (v.y - mu) * rstd * gv.y + bv.y;
    o.z = (v.z - mu) * rstd * gv.z + bv.z;
    o.w = (v.w - mu) * rstd * gv.w + bv.w;
    ((float4*)(out + (size_t)row * EE))[tid] = o;
}

// ---------------------------------------------------------------------------
// Launch
// ---------------------------------------------------------------------------
extern "C" void kernel_launch(void* const* d_in, const int* in_sizes, int n_in,
                              void* d_out, int out_size)
{
    (void)in_sizes; (void)n_in; (void)out_size;
    const float* x     = (const float*)d_in[0];
    const float* w_qkv = (const float*)d_in[1];
    const float* b_qkv = (const float*)d_in[2];
    const float* w_out = (const float*)d_in[3];
    const float* b_out = (const float*)d_in[4];
    const float* w1    = (const float*)d_in[5];
    const float* b1    = (const float*)d_in[6];
    const float* w2    = (const float*)d_in[7];
    const float* b2    = (const float*)d_in[8];
    const float* g1    = (const float*)d_in[9];
    const float* be1   = (const float*)d_in[10];
    const float* g2    = (const float*)d_in[11];
    const float* be2   = (const float*)d_in[12];
    float* out = (float*)d_out;

    float *p_qkv, *p_att, *p_r1, *p_x1, *p_h, *p_r2;
    cudaGetSymbolAddress((void**)&p_qkv, g_qkv);
    cudaGetSymbolAddress((void**)&p_att, g_att);
    cudaGetSymbolAddress((void**)&p_r1,  g_r1);
    cudaGetSymbolAddress((void**)&p_x1,  g_x1);
    cudaGetSymbolAddress((void**)&p_h,   g_h);
    cudaGetSymbolAddress((void**)&p_r2,  g_r2);

    cudaFuncSetAttribute(attn_mma, cudaFuncAttributeMaxDynamicSharedMemorySize, ATT_SMEM);
    cudaFuncSetAttribute(gemm_mma<false, false>, cudaFuncAttributeMaxDynamicSharedMemorySize, GSM_TOTAL);
    cudaFuncSetAttribute(gemm_mma<false, true>,  cudaFuncAttributeMaxDynamicSharedMemorySize, GSM_TOTAL);
    cudaFuncSetAttribute(gemm_mma<true,  false>, cudaFuncAttributeMaxDynamicSharedMemorySize, GSM_TOTAL);

    // 1) QKV projection
    gemm_mma<false, false><<<dim3(3 * EE / 128, MR / 128), 256, GSM_TOTAL>>>(
        x, w_qkv, b_qkv, nullptr, p_qkv, 3 * EE, EE);

    // 2) attention
    attn_mma<<<dim3(SS / 128, BB * HHN), 256, ATT_SMEM>>>(p_qkv, p_att);

    // 3) out-proj + residual(x)
    gemm_mma<false, true><<<dim3(EE / 128, MR / 128), 256, GSM_TOTAL>>>(
        p_att, w_out, b_out, x, p_r1, EE, EE);

    // 4) LN1
    ln_kernel<<<MR, 256>>>(p_r1, g1, be1, p_x1);

    // 5) FFN up + ReLU
    gemm_mma<true, false><<<dim3(FFD / 128, MR / 128), 256, GSM_TOTAL>>>(
        p_x1, w1, b1, nullptr, p_h, FFD, EE);

    // 6) FFN down + residual(x1)
    gemm_mma<false, true><<<dim3(EE / 128, MR / 128), 256, GSM_TOTAL>>>(
        p_h, w2, b2, p_x1, p_r2, EE, FFD);

    // 7) LN2
    ln_kernel<<<MR, 256>>>(p_r2, g2, be2, out);
}

// round 14
// speedup vs baseline: 2.1076x; 1.1778x over previous
#include <cuda_runtime.h>
#include <cuda_bf16.h>
#include <cuda_fp16.h>
#include <cstdint>
#include <math.h>

// Problem constants
#define BB   4
#define SS   2048
#define EE   1024
#define HHN  16
#define DKH  64
#define FFD  4096
#define MR   (BB*SS)   /* 8192 rows */

// ---------------------------------------------------------------------------
// Scratch
// ---------------------------------------------------------------------------
__device__ __half g_qkv_h[(size_t)MR * 3 * EE];  // 48 MB
__device__ __half g_att_h[(size_t)MR * EE];      // 16 MB
__device__ float  g_r1 [(size_t)MR * EE];        // 32 MB
__device__ float  g_x1 [(size_t)MR * EE];        // 32 MB
__device__ __half g_x1_h[(size_t)MR * EE];       // 16 MB
__device__ __half g_h_h [(size_t)MR * FFD];      // 64 MB
__device__ float  g_r2 [(size_t)MR * EE];        // 32 MB

__device__ __half g_x_h   [(size_t)MR * EE];
__device__ __half g_wqkv_h[(size_t)3 * EE * EE];
__device__ __half g_wout_h[(size_t)EE * EE];
__device__ __half g_w1_h  [(size_t)FFD * EE];
__device__ __half g_w2_h  [(size_t)EE * FFD];

// ---------------------------------------------------------------------------
// Helpers
// ---------------------------------------------------------------------------
__device__ __forceinline__ uint32_t smem_u32(const void* p) {
    uint32_t a;
    asm("{ .reg .u64 t; cvta.to.shared.u64 t, %1; cvt.u32.u64 %0, t; }"
        : "=r"(a) : "l"(p));
    return a;
}

__device__ __forceinline__ void mma16816h(float* c, const uint32_t* a, const uint32_t* b) {
    asm volatile(
        "mma.sync.aligned.m16n8k16.row.col.f32.f16.f16.f32 "
        "{%0,%1,%2,%3}, {%4,%5,%6,%7}, {%8,%9}, {%0,%1,%2,%3};"
        : "+f"(c[0]), "+f"(c[1]), "+f"(c[2]), "+f"(c[3])
        : "r"(a[0]), "r"(a[1]), "r"(a[2]), "r"(a[3]), "r"(b[0]), "r"(b[1]));
}

__device__ __forceinline__ void ldsm4(uint32_t* r, uint32_t addr) {
    asm volatile("ldmatrix.sync.aligned.m8n8.x4.shared.b16 {%0,%1,%2,%3}, [%4];"
        : "=r"(r[0]), "=r"(r[1]), "=r"(r[2]), "=r"(r[3]) : "r"(addr));
}

__device__ __forceinline__ void ldsm4t(uint32_t* r, uint32_t addr) {
    asm volatile("ldmatrix.sync.aligned.m8n8.x4.trans.shared.b16 {%0,%1,%2,%3}, [%4];"
        : "=r"(r[0]), "=r"(r[1]), "=r"(r[2]), "=r"(r[3]) : "r"(addr));
}

// ---------------------------------------------------------------------------
// fp32 -> fp16 convert kernel (weights / x, once per replay)
// ---------------------------------------------------------------------------
__global__ __launch_bounds__(256)
void cvt_kernel(const float* __restrict__ s, __half* __restrict__ d, int n4)
{
    int i = blockIdx.x * 256 + threadIdx.x;
    if (i >= n4) return;
    float4 v = ((const float4*)s)[i];
    __half2 h0 = __floats2half2_rn(v.x, v.y);
    __half2 h1 = __floats2half2_rn(v.z, v.w);
    ((uint2*)d)[i] = make_uint2(*(uint32_t*)&h0, *(uint32_t*)&h1);
}

// ---------------------------------------------------------------------------
// GEMM, fp16 in / fp16-or-fp32 out: C = A @ W^T (+bias, +res, relu)
// CTA 128x128, BK=32, 256 thr (2M x 4N warps), double-buffered.
// Loader: 4x LDG.128(fp16) + 4x STS.128 per thread per k-tile. No converts.
// ---------------------------------------------------------------------------
#define SBYTE 80
#define TILE_A 0
#define TILE_B 10240
#define STAGE  20480
#define GSM_TOTAL (2 * STAGE)

template<bool RELU, bool RES, bool OUTH>
__global__ __launch_bounds__(256, 1)
void gemm_f16(const __half* __restrict__ A, const __half* __restrict__ W,
              const float* __restrict__ bias, const float* __restrict__ res,
              float* __restrict__ C, __half* __restrict__ Ch, int N, int K)
{
    extern __shared__ char sm[];
    const int tid = threadIdx.x, lane = tid & 31, wid = tid >> 5;
    const int wm = wid & 1;
    const int wn = wid >> 1;
    const int bm = blockIdx.y * 128, bn = blockIdx.x * 128;
    const uint32_t sbase = smem_u32(sm);

    const uint32_t a_off = (uint32_t)(wm * 64 + (lane & 15)) * SBYTE + ((lane >> 4) * 16);
    const uint32_t b_off = (uint32_t)(wn * 32 + (lane & 7) + ((lane >> 4) << 3)) * SBYTE
                         + (((lane >> 3) & 1) * 16);

    // loader: 16B chunk c (8 halves), row = tid>>2 (+64*i)
    const int c = tid & 3, r0 = tid >> 2;
    const __half* Ap = A + (size_t)(bm + r0) * K + c * 8;
    const __half* Wp = W + (size_t)(bn + r0) * K + c * 8;
    const uint32_t st_off = (uint32_t)r0 * SBYTE + c * 16;

    float acc[4][4][4];
#pragma unroll
    for (int mt = 0; mt < 4; mt++)
#pragma unroll
        for (int nt = 0; nt < 4; nt++)
#pragma unroll
            for (int j = 0; j < 4; j++) acc[mt][nt][j] = 0.f;

    uint4 va[2], vb[2];
#pragma unroll
    for (int i = 0; i < 2; i++) {
        va[i] = *(const uint4*)(Ap + (size_t)(64 * i) * K);
        vb[i] = *(const uint4*)(Wp + (size_t)(64 * i) * K);
    }
#pragma unroll
    for (int i = 0; i < 2; i++) {
        uint32_t o = st_off + i * 64 * SBYTE;
        *(uint4*)(sm + TILE_A + o) = va[i];
        *(uint4*)(sm + TILE_B + o) = vb[i];
    }
    __syncthreads();

    const int KT = K >> 5;
    for (int kt = 0; kt < KT; kt++) {
        if (kt + 1 < KT) {
#pragma unroll
            for (int i = 0; i < 2; i++) {
                va[i] = *(const uint4*)(Ap + (size_t)(64 * i) * K + (kt + 1) * 32);
                vb[i] = *(const uint4*)(Wp + (size_t)(64 * i) * K + (kt + 1) * 32);
            }
        }
        const uint32_t base = sbase + (kt & 1) * STAGE;
#pragma unroll
        for (int ks = 0; ks < 2; ks++) {
            uint32_t ah[4][4], bh[2][4];
#pragma unroll
            for (int t = 0; t < 4; t++)
                ldsm4(ah[t], base + TILE_A + a_off + t * (16 * SBYTE) + ks * 32);
#pragma unroll
            for (int i = 0; i < 2; i++)
                ldsm4(bh[i], base + TILE_B + b_off + i * (16 * SBYTE) + ks * 32);
#pragma unroll
            for (int mt = 0; mt < 4; mt++)
#pragma unroll
                for (int nt = 0; nt < 4; nt++)
                    mma16816h(acc[mt][nt], ah[mt], &bh[nt >> 1][(nt & 1) * 2]);
        }
        if (kt + 1 < KT) {
            char* nb = sm + ((kt + 1) & 1) * STAGE;
#pragma unroll
            for (int i = 0; i < 2; i++) {
                uint32_t o = st_off + i * 64 * SBYTE;
                *(uint4*)(nb + TILE_A + o) = va[i];
                *(uint4*)(nb + TILE_B + o) = vb[i];
            }
        }
        __syncthreads();
    }

    const int erow = bm + wm * 64 + (lane >> 2);
    const int ecol = bn + wn * 32 + (lane & 3) * 2;
#pragma unroll
    for (int mt = 0; mt < 4; mt++)
#pragma unroll
        for (int nt = 0; nt < 4; nt++) {
            const int col = ecol + nt * 8;
            float2 bv = *(const float2*)(bias + col);
#pragma unroll
            for (int h2 = 0; h2 < 2; h2++) {
                const int row = erow + mt * 16 + h2 * 8;
                float o0 = acc[mt][nt][h2 * 2 + 0] + bv.x;
                float o1 = acc[mt][nt][h2 * 2 + 1] + bv.y;
                if (RES) {
                    float2 rv = *(const float2*)(res + (size_t)row * N + col);
                    o0 += rv.x; o1 += rv.y;
                }
                if (RELU) { o0 = fmaxf(o0, 0.f); o1 = fmaxf(o1, 0.f); }
                if (OUTH) {
                    __half2 hv = __floats2half2_rn(o0, o1);
                    *(uint32_t*)(Ch + (size_t)row * N + col) = *(uint32_t*)&hv;
                } else {
                    *(float2*)(C + (size_t)row * N + col) = make_float2(o0, o1);
                }
            }
        }
}

// ---------------------------------------------------------------------------
// Flash attention, fp16 qkv input, fp16 output.
// CTA = (b,h,128-query block), 8 warps x 16 rows, 64-key tiles.
// ---------------------------------------------------------------------------
#define ASTR   144
#define AQ     0
#define AK     (128 * ASTR)
#define AV     (AK + 64 * ASTR)
#define ATT_SMEM (AV + 64 * ASTR)   /* 36864 */

__global__ __launch_bounds__(256, 1)
void attn_mma(const __half* __restrict__ qkv, __half* __restrict__ out)
{
    extern __shared__ char sm[];
    const uint32_t sb = smem_u32(sm);
    const int tid = threadIdx.x, lane = tid & 31, w = tid >> 5;
    const int qt = blockIdx.x;
    const int bh = blockIdx.y;
    const int b = bh >> 4, h = bh & 15;

    const __half* base = qkv + (size_t)b * SS * (3 * EE);

    // Q tile [128x64] halves, scaled 1/8 (exact in fp16)
    {
        const int c8 = tid & 7, r0q = tid >> 3;   // 8 chunks x 32 rows
        const __half2 sc = __float2half2_rn(0.125f);
#pragma unroll
        for (int i = 0; i < 4; i++) {
            int r = r0q + 32 * i;
            uint4 v = *(const uint4*)(base + (size_t)(qt * 128 + r) * (3 * EE) + h * 64 + c8 * 8);
            __half2* hp = (__half2*)&v;
#pragma unroll
            for (int j = 0; j < 4; j++) hp[j] = __hmul2(hp[j], sc);
            *(uint4*)(sm + AQ + (uint32_t)r * ASTR + c8 * 16) = v;
        }
    }

    const int c8 = tid & 7, kr0 = tid >> 3;       // 8 chunks x 32 rows
    const __half* kbase = base + EE + h * 64 + c8 * 8;
    const __half* vbase = kbase + EE;

    uint4 kreg[2], vreg[2];
#pragma unroll
    for (int i = 0; i < 2; i++) {
        kreg[i] = *(const uint4*)(kbase + (size_t)(kr0 + 32 * i) * (3 * EE));
        vreg[i] = *(const uint4*)(vbase + (size_t)(kr0 + 32 * i) * (3 * EE));
    }
#pragma unroll
    for (int i = 0; i < 2; i++) {
        uint32_t o = (uint32_t)(kr0 + 32 * i) * ASTR + c8 * 16;
        *(uint4*)(sm + AK + o) = kreg[i];
        *(uint4*)(sm + AV + o) = vreg[i];
    }
    __syncthreads();

    const uint32_t a_off = (uint32_t)(w * 16 + (lane & 15)) * ASTR + ((lane >> 4) * 16);
    const uint32_t b_off = (uint32_t)((lane & 7) + ((lane >> 4) << 3)) * ASTR
                         + (((lane >> 3) & 1) * 16);
    const uint32_t v_off = (uint32_t)(lane & 15) * ASTR + ((lane >> 4) * 16);

    float mA = -1e30f, mB = -1e30f, lA = 0.f, lB = 0.f;
    float O[8][4];
#pragma unroll
    for (int j = 0; j < 8; j++)
#pragma unroll
        for (int k = 0; k < 4; k++) O[j][k] = 0.f;

    const int NT = SS / 64;
    for (int kt = 0; kt < NT; kt++) {
        const bool more = (kt + 1 < NT);
        if (more) {
#pragma unroll
            for (int i = 0; i < 2; i++) {
                kreg[i] = *(const uint4*)(kbase + (size_t)((kt + 1) * 64 + kr0 + 32 * i) * (3 * EE));
                vreg[i] = *(const uint4*)(vbase + (size_t)((kt + 1) * 64 + kr0 + 32 * i) * (3 * EE));
            }
        }

        // ---- S = Q K^T ----
        float S[8][4];
#pragma unroll
        for (int j = 0; j < 8; j++)
#pragma unroll
            for (int k = 0; k < 4; k++) S[j][k] = 0.f;

#pragma unroll
        for (int kd = 0; kd < 4; kd++) {
            uint32_t ah[4];
            ldsm4(ah, sb + AQ + a_off + kd * 32);
#pragma unroll
            for (int i = 0; i < 4; i++) {
                uint32_t bh4[4];
                ldsm4(bh4, sb + AK + b_off + i * (16 * ASTR) + kd * 32);
                mma16816h(S[2 * i],     ah, &bh4[0]);
                mma16816h(S[2 * i + 1], ah, &bh4[2]);
            }
        }

        // ---- online softmax ----
        float txA = -1e30f, txB = -1e30f;
#pragma unroll
        for (int j = 0; j < 8; j++) {
            txA = fmaxf(txA, fmaxf(S[j][0], S[j][1]));
            txB = fmaxf(txB, fmaxf(S[j][2], S[j][3]));
        }
        txA = fmaxf(txA, __shfl_xor_sync(0xffffffffu, txA, 1));
        txA = fmaxf(txA, __shfl_xor_sync(0xffffffffu, txA, 2));
        txB = fmaxf(txB, __shfl_xor_sync(0xffffffffu, txB, 1));
        txB = fmaxf(txB, __shfl_xor_sync(0xffffffffu, txB, 2));
        const float mnA = fmaxf(mA, txA), mnB = fmaxf(mB, txB);
        const float cA = __expf(mA - mnA), cB = __expf(mB - mnB);

        float sA = 0.f, sB = 0.f;
#pragma unroll
        for (int j = 0; j < 8; j++) {
            S[j][0] = __expf(S[j][0] - mnA);
            S[j][1] = __expf(S[j][1] - mnA);
            S[j][2] = __expf(S[j][2] - mnB);
            S[j][3] = __expf(S[j][3] - mnB);
            sA += S[j][0] + S[j][1];
            sB += S[j][2] + S[j][3];
        }
        sA += __shfl_xor_sync(0xffffffffu, sA, 1);
        sA += __shfl_xor_sync(0xffffffffu, sA, 2);
        sB += __shfl_xor_sync(0xffffffffu, sB, 1);
        sB += __shfl_xor_sync(0xffffffffu, sB, 2);
        lA = lA * cA + sA;  mA = mnA;
        lB = lB * cB + sB;  mB = mnB;
#pragma unroll
        for (int j = 0; j < 8; j++) {
            O[j][0] *= cA; O[j][1] *= cA;
            O[j][2] *= cB; O[j][3] *= cB;
        }

        // ---- O += P V ----
#pragma unroll
        for (int kk = 0; kk < 4; kk++) {
            uint32_t ph[4];
#pragma unroll
            for (int u = 0; u < 2; u++) {
                const float* sp = S[2 * kk + u];
                __half2 p0 = __floats2half2_rn(sp[0], sp[1]);
                __half2 p1 = __floats2half2_rn(sp[2], sp[3]);
                ph[2 * u]     = *(uint32_t*)&p0;
                ph[2 * u + 1] = *(uint32_t*)&p1;
            }
#pragma unroll
            for (int dimc = 0; dimc < 4; dimc++) {
                uint32_t vh[4];
                ldsm4t(vh, sb + AV + v_off + (uint32_t)(kk * 16) * ASTR + dimc * 32);
                mma16816h(O[2 * dimc],     ph, &vh[0]);
                mma16816h(O[2 * dimc + 1], ph, &vh[2]);
            }
        }

        __syncthreads();
        if (more) {
#pragma unroll
            for (int i = 0; i < 2; i++) {
                uint32_t o = (uint32_t)(kr0 + 32 * i) * ASTR + c8 * 16;
                *(uint4*)(sm + AK + o) = kreg[i];
                *(uint4*)(sm + AV + o) = vreg[i];
            }
            __syncthreads();
        }
    }

    const float invA = 1.f / lA, invB = 1.f / lB;
    const size_t rowA = (size_t)b * SS + qt * 128 + w * 16 + (lane >> 2);
    __half* oA = out + rowA * EE + h * 64 + (lane & 3) * 2;
    __half* oB = oA + (size_t)8 * EE;
#pragma unroll
    for (int j = 0; j < 8; j++) {
        __half2 a2 = __floats2half2_rn(O[j][0] * invA, O[j][1] * invA);
        __half2 b2 = __floats2half2_rn(O[j][2] * invB, O[j][3] * invB);
        *(uint32_t*)(oA + j * 8) = *(uint32_t*)&a2;
        *(uint32_t*)(oB + j * 8) = *(uint32_t*)&b2;
    }
}

// ---------------------------------------------------------------------------
// LayerNorm — optionally emits fp16 alongside fp32
// ---------------------------------------------------------------------------
template<bool EMITH>
__global__ __launch_bounds__(256)
void ln_kernel(const float* __restrict__ r, const float* __restrict__ g,
               const float* __restrict__ be, float* __restrict__ out,
               __half* __restrict__ oh)
{
    const int row = blockIdx.x;
    const int tid = threadIdx.x;
    const int lane = tid & 31, warp = tid >> 5;

    float4 v = ((const float4*)(r + (size_t)row * EE))[tid];
    float s  = v.x + v.y + v.z + v.w;
    float sq = v.x * v.x + v.y * v.y + v.z * v.z + v.w * v.w;
#pragma unroll
    for (int o = 16; o; o >>= 1) {
        s  += __shfl_xor_sync(0xffffffffu, s,  o);
        sq += __shfl_xor_sync(0xffffffffu, sq, o);
    }
    __shared__ float ss[8], ssq[8];
    if (lane == 0) { ss[warp] = s; ssq[warp] = sq; }
    __syncthreads();
    float ts = 0.f, tq = 0.f;
#pragma unroll
    for (int i = 0; i < 8; i++) { ts += ss[i]; tq += ssq[i]; }
    float mu   = ts * (1.0f / EE);
    float var  = tq * (1.0f / EE) - mu * mu;
    float rstd = rsqrtf(var + 1e-5f);

    float4 gv = ((const float4*)g)[tid];
    float4 bv = ((const float4*)be)[tid];
    float4 o;
    o.x = (v.x - mu) * rstd * gv.x + bv.x;
    o.y = (v.y - mu) * rstd * gv.y + bv.y;
    o.z = (v.z - mu) * rstd * gv.z + bv.z;
    o.w = (v.w - mu) * rstd * gv.w + bv.w;
    ((float4*)(out + (size_t)row * EE))[tid] = o;
    if (EMITH) {
        __half2 h0 = __floats2half2_rn(o.x, o.y);
        __half2 h1 = __floats2half2_rn(o.z, o.w);
        ((uint2*)(oh + (size_t)row * EE))[tid] = make_uint2(*(uint32_t*)&h0, *(uint32_t*)&h1);
    }
}

// ---------------------------------------------------------------------------
// Launch
// ---------------------------------------------------------------------------
extern "C" void kernel_launch(void* const* d_in, const int* in_sizes, int n_in,
                              void* d_out, int out_size)
{
    (void)in_sizes; (void)n_in; (void)out_size;
    const float* x     = (const float*)d_in[0];
    const float* w_qkv = (const float*)d_in[1];
    const float* b_qkv = (const float*)d_in[2];
    const float* w_out = (const float*)d_in[3];
    const float* b_out = (const float*)d_in[4];
    const float* w1    = (const float*)d_in[5];
    const float* b1    = (const float*)d_in[6];
    const float* w2    = (const float*)d_in[7];
    const float* b2    = (const float*)d_in[8];
    const float* g1    = (const float*)d_in[9];
    const float* be1   = (const float*)d_in[10];
    const float* g2    = (const float*)d_in[11];
    const float* be2   = (const float*)d_in[12];
    float* out = (float*)d_out;

    float *p_r1, *p_x1, *p_r2;
    __half *p_qkvh, *p_atth, *p_x1h, *p_hh, *p_xh;
    __half *p_wqh, *p_woh, *p_w1h, *p_w2h;
    cudaGetSymbolAddress((void**)&p_qkvh, g_qkv_h);
    cudaGetSymbolAddress((void**)&p_atth, g_att_h);
    cudaGetSymbolAddress((void**)&p_r1,   g_r1);
    cudaGetSymbolAddress((void**)&p_x1,   g_x1);
    cudaGetSymbolAddress((void**)&p_x1h,  g_x1_h);
    cudaGetSymbolAddress((void**)&p_hh,   g_h_h);
    cudaGetSymbolAddress((void**)&p_r2,   g_r2);
    cudaGetSymbolAddress((void**)&p_xh,   g_x_h);
    cudaGetSymbolAddress((void**)&p_wqh,  g_wqkv_h);
    cudaGetSymbolAddress((void**)&p_woh,  g_wout_h);
    cudaGetSymbolAddress((void**)&p_w1h,  g_w1_h);
    cudaGetSymbolAddress((void**)&p_w2h,  g_w2_h);

    cudaFuncSetAttribute(attn_mma, cudaFuncAttributeMaxDynamicSharedMemorySize, ATT_SMEM);
    cudaFuncSetAttribute(gemm_f16<false, false, true>,  cudaFuncAttributeMaxDynamicSharedMemorySize, GSM_TOTAL);
    cudaFuncSetAttribute(gemm_f16<false, true,  false>, cudaFuncAttributeMaxDynamicSharedMemorySize, GSM_TOTAL);
    cudaFuncSetAttribute(gemm_f16<true,  false, true>,  cudaFuncAttributeMaxDynamicSharedMemorySize, GSM_TOTAL);

    // 0) fp32 -> fp16 conversions (x + weights)
    cvt_kernel<<<(MR * EE / 4) / 256, 256>>>(x, p_xh, MR * EE / 4);
    cvt_kernel<<<(3 * EE * EE / 4) / 256, 256>>>(w_qkv, p_wqh, 3 * EE * EE / 4);
    cvt_kernel<<<(EE * EE / 4) / 256, 256>>>(w_out, p_woh, EE * EE / 4);
    cvt_kernel<<<(FFD * EE / 4) / 256, 256>>>(w1, p_w1h, FFD * EE / 4);
    cvt_kernel<<<(EE * FFD / 4) / 256, 256>>>(w2, p_w2h, EE * FFD / 4);

    // 1) QKV projection -> fp16
    gemm_f16<false, false, true><<<dim3(3 * EE / 128, MR / 128), 256, GSM_TOTAL>>>(
        p_xh, p_wqh, b_qkv, nullptr, nullptr, p_qkvh, 3 * EE, EE);

    // 2) attention -> fp16
    attn_mma<<<dim3(SS / 128, BB * HHN), 256, ATT_SMEM>>>(p_qkvh, p_atth);

    // 3) out-proj + residual(x) -> r1 fp32
    gemm_f16<false, true, false><<<dim3(EE / 128, MR / 128), 256, GSM_TOTAL>>>(
        p_atth, p_woh, b_out, x, p_r1, nullptr, EE, EE);

    // 4) LN1 -> x1 fp32 + fp16
    ln_kernel<true><<<MR, 256>>>(p_r1, g1, be1, p_x1, p_x1h);

    // 5) FFN up + ReLU -> h fp16
    gemm_f16<true, false, true><<<dim3(FFD / 128, MR / 128), 256, GSM_TOTAL>>>(
        p_x1h, p_w1h, b1, nullptr, nullptr, p_hh, FFD, EE);

    // 6) FFN down + residual(x1) -> r2 fp32
    gemm_f16<false, true, false><<<dim3(EE / 128, MR / 128), 256, GSM_TOTAL>>>(
        p_hh, p_w2h, b2, p_x1, p_r2, nullptr, EE, FFD);

    // 7) LN2 -> out
    ln_kernel<false><<<MR, 256>>>(p_r2, g2, be2, out, nullptr);
}

// round 17
// speedup vs baseline: 2.5027x; 1.1875x over previous
#include <cuda_runtime.h>
#include <cuda_bf16.h>
#include <cuda_fp16.h>
#include <cstdint>
#include <math.h>

// Problem constants
#define BB   4
#define SS   2048
#define EE   1024
#define HHN  16
#define DKH  64
#define FFD  4096
#define MR   (BB*SS)   /* 8192 rows */

// ---------------------------------------------------------------------------
// Scratch
// ---------------------------------------------------------------------------
__device__ __half g_qkv_h[(size_t)MR * 3 * EE];  // 48 MB
__device__ __half g_att_h[(size_t)MR * EE];      // 16 MB
__device__ float  g_r1 [(size_t)MR * EE];        // 32 MB
__device__ float  g_x1 [(size_t)MR * EE];        // 32 MB
__device__ __half g_x1_h[(size_t)MR * EE];       // 16 MB
__device__ __half g_h_h [(size_t)MR * FFD];      // 64 MB
__device__ float  g_r2 [(size_t)MR * EE];        // 32 MB

__device__ __half g_x_h   [(size_t)MR * EE];
__device__ __half g_wqkv_h[(size_t)3 * EE * EE];
__device__ __half g_wout_h[(size_t)EE * EE];
__device__ __half g_w1_h  [(size_t)FFD * EE];
__device__ __half g_w2_h  [(size_t)EE * FFD];

// ---------------------------------------------------------------------------
// Helpers
// ---------------------------------------------------------------------------
__device__ __forceinline__ uint32_t smem_u32(const void* p) {
    uint32_t a;
    asm("{ .reg .u64 t; cvta.to.shared.u64 t, %1; cvt.u32.u64 %0, t; }"
        : "=r"(a) : "l"(p));
    return a;
}

__device__ __forceinline__ void mma16816h(float* c, const uint32_t* a, const uint32_t* b) {
    asm volatile(
        "mma.sync.aligned.m16n8k16.row.col.f32.f16.f16.f32 "
        "{%0,%1,%2,%3}, {%4,%5,%6,%7}, {%8,%9}, {%0,%1,%2,%3};"
        : "+f"(c[0]), "+f"(c[1]), "+f"(c[2]), "+f"(c[3])
        : "r"(a[0]), "r"(a[1]), "r"(a[2]), "r"(a[3]), "r"(b[0]), "r"(b[1]));
}

__device__ __forceinline__ void ldsm4(uint32_t* r, uint32_t addr) {
    asm volatile("ldmatrix.sync.aligned.m8n8.x4.shared.b16 {%0,%1,%2,%3}, [%4];"
        : "=r"(r[0]), "=r"(r[1]), "=r"(r[2]), "=r"(r[3]) : "r"(addr));
}

__device__ __forceinline__ void ldsm4t(uint32_t* r, uint32_t addr) {
    asm volatile("ldmatrix.sync.aligned.m8n8.x4.trans.shared.b16 {%0,%1,%2,%3}, [%4];"
        : "=r"(r[0]), "=r"(r[1]), "=r"(r[2]), "=r"(r[3]) : "r"(addr));
}

// ---------------------------------------------------------------------------
// fp32 -> fp16 convert kernel
// ---------------------------------------------------------------------------
__global__ __launch_bounds__(256)
void cvt_kernel(const float* __restrict__ s, __half* __restrict__ d, int n4)
{
    int i = blockIdx.x * 256 + threadIdx.x;
    if (i >= n4) return;
    float4 v = ((const float4*)s)[i];
    __half2 h0 = __floats2half2_rn(v.x, v.y);
    __half2 h1 = __floats2half2_rn(v.z, v.w);
    ((uint2*)d)[i] = make_uint2(*(uint32_t*)&h0, *(uint32_t*)&h1);
}

// ---------------------------------------------------------------------------
// GEMM, fp16 in: C = A @ W^T (+bias, +res, relu)
// CTA 256x128, BK=32, 256 thr (8 warps = 2M x 4N, warp tile 128x32), dbl-buf.
// ---------------------------------------------------------------------------
#define SBYTE 80
#define TILE_A 0
#define TILE_B 20480
#define STAGE  30720
#define GSM_TOTAL (2 * STAGE)

template<bool RELU, bool RES, bool OUTH>
__global__ __launch_bounds__(256, 1)
void gemm_f16(const __half* __restrict__ A, const __half* __restrict__ W,
              const float* __restrict__ bias, const float* __restrict__ res,
              float* __restrict__ C, __half* __restrict__ Ch, int N, int K)
{
    extern __shared__ char sm[];
    const int tid = threadIdx.x, lane = tid & 31, wid = tid >> 5;
    const int wm = wid & 1;        // M half (128 rows)
    const int wn = wid >> 1;       // N quarter (32 cols)
    const int bm = blockIdx.y * 256, bn = blockIdx.x * 128;
    const uint32_t sbase = smem_u32(sm);

    const uint32_t a_off = (uint32_t)(wm * 128 + (lane & 15)) * SBYTE + ((lane >> 4) * 16);
    const uint32_t b_off = (uint32_t)(wn * 32 + (lane & 7) + ((lane >> 4) << 3)) * SBYTE
                         + (((lane >> 3) & 1) * 16);

    // loader: 16B chunk c, rows r0 + 64*i (A: i=0..3, B: i=0..1)
    const int c = tid & 3, r0 = tid >> 2;
    const __half* Ap = A + (size_t)(bm + r0) * K + c * 8;
    const __half* Wp = W + (size_t)(bn + r0) * K + c * 8;
    const uint32_t st_off = (uint32_t)r0 * SBYTE + c * 16;

    float acc[8][4][4];
#pragma unroll
    for (int mt = 0; mt < 8; mt++)
#pragma unroll
        for (int nt = 0; nt < 4; nt++)
#pragma unroll
            for (int j = 0; j < 4; j++) acc[mt][nt][j] = 0.f;

    uint4 va[4], vb[2];
#pragma unroll
    for (int i = 0; i < 4; i++)
        va[i] = *(const uint4*)(Ap + (size_t)(64 * i) * K);
#pragma unroll
    for (int i = 0; i < 2; i++)
        vb[i] = *(const uint4*)(Wp + (size_t)(64 * i) * K);
#pragma unroll
    for (int i = 0; i < 4; i++)
        *(uint4*)(sm + TILE_A + st_off + i * 64 * SBYTE) = va[i];
#pragma unroll
    for (int i = 0; i < 2; i++)
        *(uint4*)(sm + TILE_B + st_off + i * 64 * SBYTE) = vb[i];
    __syncthreads();

    const int KT = K >> 5;
    for (int kt = 0; kt < KT; kt++) {
        if (kt + 1 < KT) {
#pragma unroll
            for (int i = 0; i < 4; i++)
                va[i] = *(const uint4*)(Ap + (size_t)(64 * i) * K + (kt + 1) * 32);
#pragma unroll
            for (int i = 0; i < 2; i++)
                vb[i] = *(const uint4*)(Wp + (size_t)(64 * i) * K + (kt + 1) * 32);
        }
        const uint32_t base = sbase + (kt & 1) * STAGE;
#pragma unroll
        for (int ks = 0; ks < 2; ks++) {
            uint32_t bh[2][4];
#pragma unroll
            for (int i = 0; i < 2; i++)
                ldsm4(bh[i], base + TILE_B + b_off + i * (16 * SBYTE) + ks * 32);
#pragma unroll
            for (int mt = 0; mt < 8; mt++) {
                uint32_t ah[4];
                ldsm4(ah, base + TILE_A + a_off + mt * (16 * SBYTE) + ks * 32);
#pragma unroll
                for (int nt = 0; nt < 4; nt++)
                    mma16816h(acc[mt][nt], ah, &bh[nt >> 1][(nt & 1) * 2]);
            }
        }
        if (kt + 1 < KT) {
            char* nb = sm + ((kt + 1) & 1) * STAGE;
#pragma unroll
            for (int i = 0; i < 4; i++)
                *(uint4*)(nb + TILE_A + st_off + i * 64 * SBYTE) = va[i];
#pragma unroll
            for (int i = 0; i < 2; i++)
                *(uint4*)(nb + TILE_B + st_off + i * 64 * SBYTE) = vb[i];
        }
        __syncthreads();
    }

    const int erow = bm + wm * 128 + (lane >> 2);
    const int ecol = bn + wn * 32 + (lane & 3) * 2;
#pragma unroll
    for (int mt = 0; mt < 8; mt++)
#pragma unroll
        for (int nt = 0; nt < 4; nt++) {
            const int col = ecol + nt * 8;
            float2 bv = *(const float2*)(bias + col);
#pragma unroll
            for (int h2 = 0; h2 < 2; h2++) {
                const int row = erow + mt * 16 + h2 * 8;
                float o0 = acc[mt][nt][h2 * 2 + 0] + bv.x;
                float o1 = acc[mt][nt][h2 * 2 + 1] + bv.y;
                if (RES) {
                    float2 rv = *(const float2*)(res + (size_t)row * N + col);
                    o0 += rv.x; o1 += rv.y;
                }
                if (RELU) { o0 = fmaxf(o0, 0.f); o1 = fmaxf(o1, 0.f); }
                if (OUTH) {
                    __half2 hv = __floats2half2_rn(o0, o1);
                    *(uint32_t*)(Ch + (size_t)row * N + col) = *(uint32_t*)&hv;
                } else {
                    *(float2*)(C + (size_t)row * N + col) = make_float2(o0, o1);
                }
            }
        }
}

// ---------------------------------------------------------------------------
// Flash attention, fp16 qkv in / fp16 out.
// K/V double-buffered in smem -> ONE __syncthreads per 64-key tile.
// ---------------------------------------------------------------------------
#define ASTR   144
#define AQ     0
#define AKV0   (128 * ASTR)                 /* stage 0: K then V */
#define AKV1   (AKV0 + 2 * 64 * ASTR)       /* stage 1 */
#define KVSZ   (64 * ASTR)
#define ATT_SMEM (AKV1 + 2 * 64 * ASTR)     /* 55296 */

__global__ __launch_bounds__(256, 1)
void attn_mma(const __half* __restrict__ qkv, __half* __restrict__ out)
{
    extern __shared__ char sm[];
    const uint32_t sb = smem_u32(sm);
    const int tid = threadIdx.x, lane = tid & 31, w = tid >> 5;
    const int qt = blockIdx.x;
    const int bh = blockIdx.y;
    const int b = bh >> 4, h = bh & 15;

    const __half* base = qkv + (size_t)b * SS * (3 * EE);

    // Q tile [128x64] halves, scaled 1/8 (exact in fp16)
    {
        const int c8 = tid & 7, r0q = tid >> 3;
        const __half2 sc = __float2half2_rn(0.125f);
#pragma unroll
        for (int i = 0; i < 4; i++) {
            int r = r0q + 32 * i;
            uint4 v = *(const uint4*)(base + (size_t)(qt * 128 + r) * (3 * EE) + h * 64 + c8 * 8);
            __half2* hp = (__half2*)&v;
#pragma unroll
            for (int j = 0; j < 4; j++) hp[j] = __hmul2(hp[j], sc);
            *(uint4*)(sm + AQ + (uint32_t)r * ASTR + c8 * 16) = v;
        }
    }

    const int c8 = tid & 7, kr0 = tid >> 3;
    const __half* kbase = base + EE + h * 64 + c8 * 8;
    const __half* vbase = kbase + EE;

    uint4 kreg[2], vreg[2];
#pragma unroll
    for (int i = 0; i < 2; i++) {
        kreg[i] = *(const uint4*)(kbase + (size_t)(kr0 + 32 * i) * (3 * EE));
        vreg[i] = *(const uint4*)(vbase + (size_t)(kr0 + 32 * i) * (3 * EE));
    }
#pragma unroll
    for (int i = 0; i < 2; i++) {
        uint32_t o = (uint32_t)(kr0 + 32 * i) * ASTR + c8 * 16;
        *(uint4*)(sm + AKV0 + o) = kreg[i];
        *(uint4*)(sm + AKV0 + KVSZ + o) = vreg[i];
    }
    __syncthreads();

    const uint32_t a_off = (uint32_t)(w * 16 + (lane & 15)) * ASTR + ((lane >> 4) * 16);
    const uint32_t b_off = (uint32_t)((lane & 7) + ((lane >> 4) << 3)) * ASTR
                         + (((lane >> 3) & 1) * 16);
    const uint32_t v_off = (uint32_t)(lane & 15) * ASTR + ((lane >> 4) * 16);

    float mA = -1e30f, mB = -1e30f, lA = 0.f, lB = 0.f;
    float O[8][4];
#pragma unroll
    for (int j = 0; j < 8; j++)
#pragma unroll
        for (int k = 0; k < 4; k++) O[j][k] = 0.f;

    const int NT = SS / 64;
    for (int kt = 0; kt < NT; kt++) {
        const bool more = (kt + 1 < NT);
        const uint32_t AK = (kt & 1) ? AKV1 : AKV0;
        const uint32_t AV = AK + KVSZ;
        if (more) {
#pragma unroll
            for (int i = 0; i < 2; i++) {
                kreg[i] = *(const uint4*)(kbase + (size_t)((kt + 1) * 64 + kr0 + 32 * i) * (3 * EE));
                vreg[i] = *(const uint4*)(vbase + (size_t)((kt + 1) * 64 + kr0 + 32 * i) * (3 * EE));
            }
        }

        // ---- S = Q K^T ----
        float S[8][4];
#pragma unroll
        for (int j = 0; j < 8; j++)
#pragma unroll
            for (int k = 0; k < 4; k++) S[j][k] = 0.f;

#pragma unroll
        for (int kd = 0; kd < 4; kd++) {
            uint32_t ah[4];
            ldsm4(ah, sb + AQ + a_off + kd * 32);
#pragma unroll
            for (int i = 0; i < 4; i++) {
                uint32_t bh4[4];
                ldsm4(bh4, sb + AK + b_off + i * (16 * ASTR) + kd * 32);
                mma16816h(S[2 * i],     ah, &bh4[0]);
                mma16816h(S[2 * i + 1], ah, &bh4[2]);
            }
        }

        // ---- online softmax ----
        float txA = -1e30f, txB = -1e30f;
#pragma unroll
        for (int j = 0; j < 8; j++) {
            txA = fmaxf(txA, fmaxf(S[j][0], S[j][1]));
            txB = fmaxf(txB, fmaxf(S[j][2], S[j][3]));
        }
        txA = fmaxf(txA, __shfl_xor_sync(0xffffffffu, txA, 1));
        txA = fmaxf(txA, __shfl_xor_sync(0xffffffffu, txA, 2));
        txB = fmaxf(txB, __shfl_xor_sync(0xffffffffu, txB, 1));
        txB = fmaxf(txB, __shfl_xor_sync(0xffffffffu, txB, 2));
        const float mnA = fmaxf(mA, txA), mnB = fmaxf(mB, txB);
        const float cA = __expf(mA - mnA), cB = __expf(mB - mnB);

        float sA = 0.f, sB = 0.f;
#pragma unroll
        for (int j = 0; j < 8; j++) {
            S[j][0] = __expf(S[j][0] - mnA);
            S[j][1] = __expf(S[j][1] - mnA);
            S[j][2] = __expf(S[j][2] - mnB);
            S[j][3] = __expf(S[j][3] - mnB);
            sA += S[j][0] + S[j][1];
            sB += S[j][2] + S[j][3];
        }
        sA += __shfl_xor_sync(0xffffffffu, sA, 1);
        sA += __shfl_xor_sync(0xffffffffu, sA, 2);
        sB += __shfl_xor_sync(0xffffffffu, sB, 1);
        sB += __shfl_xor_sync(0xffffffffu, sB, 2);
        lA = lA * cA + sA;  mA = mnA;
        lB = lB * cB + sB;  mB = mnB;
#pragma unroll
        for (int j = 0; j < 8; j++) {
            O[j][0] *= cA; O[j][1] *= cA;
            O[j][2] *= cB; O[j][3] *= cB;
        }

        // ---- O += P V ----
#pragma unroll
        for (int kk = 0; kk < 4; kk++) {
            uint32_t ph[4];
#pragma unroll
            for (int u = 0; u < 2; u++) {
                const float* sp = S[2 * kk + u];
                __half2 p0 = __floats2half2_rn(sp[0], sp[1]);
                __half2 p1 = __floats2half2_rn(sp[2], sp[3]);
                ph[2 * u]     = *(uint32_t*)&p0;
                ph[2 * u + 1] = *(uint32_t*)&p1;
            }
#pragma unroll
            for (int dimc = 0; dimc < 4; dimc++) {
                uint32_t vh[4];
                ldsm4t(vh, sb + AV + v_off + (uint32_t)(kk * 16) * ASTR + dimc * 32);
                mma16816h(O[2 * dimc],     ph, &vh[0]);
                mma16816h(O[2 * dimc + 1], ph, &vh[2]);
            }
        }

        // store next tile into the OTHER stage; one barrier per tile
        if (more) {
            const uint32_t NK = (kt & 1) ? AKV0 : AKV1;
#pragma unroll
            for (int i = 0; i < 2; i++) {
                uint32_t o = (uint32_t)(kr0 + 32 * i) * ASTR + c8 * 16;
                *(uint4*)(sm + NK + o) = kreg[i];
                *(uint4*)(sm + NK + KVSZ + o) = vreg[i];
            }
        }
        __syncthreads();
    }

    const float invA = 1.f / lA, invB = 1.f / lB;
    const size_t rowA = (size_t)b * SS + qt * 128 + w * 16 + (lane >> 2);
    __half* oA = out + rowA * EE + h * 64 + (lane & 3) * 2;
    __half* oB = oA + (size_t)8 * EE;
#pragma unroll
    for (int j = 0; j < 8; j++) {
        __half2 a2 = __floats2half2_rn(O[j][0] * invA, O[j][1] * invA);
        __half2 b2 = __floats2half2_rn(O[j][2] * invB, O[j][3] * invB);
        *(uint32_t*)(oA + j * 8) = *(uint32_t*)&a2;
        *(uint32_t*)(oB + j * 8) = *(uint32_t*)&b2;
    }
}

// ---------------------------------------------------------------------------
// LayerNorm — optionally emits fp16 alongside fp32
// ---------------------------------------------------------------------------
template<bool EMITH>
__global__ __launch_bounds__(256)
void ln_kernel(const float* __restrict__ r, const float* __restrict__ g,
               const float* __restrict__ be, float* __restrict__ out,
               __half* __restrict__ oh)
{
    const int row = blockIdx.x;
    const int tid = threadIdx.x;
    const int lane = tid & 31, warp = tid >> 5;

    float4 v = ((const float4*)(r + (size_t)row * EE))[tid];
    float s  = v.x + v.y + v.z + v.w;
    float sq = v.x * v.x + v.y * v.y + v.z * v.z + v.w * v.w;
#pragma unroll
    for (int o = 16; o; o >>= 1) {
        s  += __shfl_xor_sync(0xffffffffu, s,  o);
        sq += __shfl_xor_sync(0xffffffffu, sq, o);
    }
    __shared__ float ss[8], ssq[8];
    if (lane == 0) { ss[warp] = s; ssq[warp] = sq; }
    __syncthreads();
    float ts = 0.f, tq = 0.f;
#pragma unroll
    for (int i = 0; i < 8; i++) { ts += ss[i]; tq += ssq[i]; }
    float mu   = ts * (1.0f / EE);
    float var  = tq * (1.0f / EE) - mu * mu;
    float rstd = rsqrtf(var + 1e-5f);

    float4 gv = ((const float4*)g)[tid];
    float4 bv = ((const float4*)be)[tid];
    float4 o;
    o.x = (v.x - mu) * rstd * gv.x + bv.x;
    o.y = (v.y - mu) * rstd * gv.y + bv.y;
    o.z = (v.z - mu) * rstd * gv.z + bv.z;
    o.w = (v.w - mu) * rstd * gv.w + bv.w;
    ((float4*)(out + (size_t)row * EE))[tid] = o;
    if (EMITH) {
        __half2 h0 = __floats2half2_rn(o.x, o.y);
        __half2 h1 = __floats2half2_rn(o.z, o.w);
        ((uint2*)(oh + (size_t)row * EE))[tid] = make_uint2(*(uint32_t*)&h0, *(uint32_t*)&h1);
    }
}

// ---------------------------------------------------------------------------
// Launch
// ---------------------------------------------------------------------------
extern "C" void kernel_launch(void* const* d_in, const int* in_sizes, int n_in,
                              void* d_out, int out_size)
{
    (void)in_sizes; (void)n_in; (void)out_size;
    const float* x     = (const float*)d_in[0];
    const float* w_qkv = (const float*)d_in[1];
    const float* b_qkv = (const float*)d_in[2];
    const float* w_out = (const float*)d_in[3];
    const float* b_out = (const float*)d_in[4];
    const float* w1    = (const float*)d_in[5];
    const float* b1    = (const float*)d_in[6];
    const float* w2    = (const float*)d_in[7];
    const float* b2    = (const float*)d_in[8];
    const float* g1    = (const float*)d_in[9];
    const float* be1   = (const float*)d_in[10];
    const float* g2    = (const float*)d_in[11];
    const float* be2   = (const float*)d_in[12];
    float* out = (float*)d_out;

    float *p_r1, *p_x1, *p_r2;
    __half *p_qkvh, *p_atth, *p_x1h, *p_hh, *p_xh;
    __half *p_wqh, *p_woh, *p_w1h, *p_w2h;
    cudaGetSymbolAddress((void**)&p_qkvh, g_qkv_h);
    cudaGetSymbolAddress((void**)&p_atth, g_att_h);
    cudaGetSymbolAddress((void**)&p_r1,   g_r1);
    cudaGetSymbolAddress((void**)&p_x1,   g_x1);
    cudaGetSymbolAddress((void**)&p_x1h,  g_x1_h);
    cudaGetSymbolAddress((void**)&p_hh,   g_h_h);
    cudaGetSymbolAddress((void**)&p_r2,   g_r2);
    cudaGetSymbolAddress((void**)&p_xh,   g_x_h);
    cudaGetSymbolAddress((void**)&p_wqh,  g_wqkv_h);
    cudaGetSymbolAddress((void**)&p_woh,  g_wout_h);
    cudaGetSymbolAddress((void**)&p_w1h,  g_w1_h);
    cudaGetSymbolAddress((void**)&p_w2h,  g_w2_h);

    cudaFuncSetAttribute(attn_mma, cudaFuncAttributeMaxDynamicSharedMemorySize, ATT_SMEM);
    cudaFuncSetAttribute(gemm_f16<false, false, true>,  cudaFuncAttributeMaxDynamicSharedMemorySize, GSM_TOTAL);
    cudaFuncSetAttribute(gemm_f16<false, true,  false>, cudaFuncAttributeMaxDynamicSharedMemorySize, GSM_TOTAL);
    cudaFuncSetAttribute(gemm_f16<true,  false, true>,  cudaFuncAttributeMaxDynamicSharedMemorySize, GSM_TOTAL);

    // 0) fp32 -> fp16 conversions
    cvt_kernel<<<(MR * EE / 4) / 256, 256>>>(x, p_xh, MR * EE / 4);
    cvt_kernel<<<(3 * EE * EE / 4) / 256, 256>>>(w_qkv, p_wqh, 3 * EE * EE / 4);
    cvt_kernel<<<(EE * EE / 4) / 256, 256>>>(w_out, p_woh, EE * EE / 4);
    cvt_kernel<<<(FFD * EE / 4) / 256, 256>>>(w1, p_w1h, FFD * EE / 4);
    cvt_kernel<<<(EE * FFD / 4) / 256, 256>>>(w2, p_w2h, EE * FFD / 4);

    // 1) QKV projection -> fp16
    gemm_f16<false, false, true><<<dim3(3 * EE / 128, MR / 256), 256, GSM_TOTAL>>>(
        p_xh, p_wqh, b_qkv, nullptr, nullptr, p_qkvh, 3 * EE, EE);

    // 2) attention -> fp16
    attn_mma<<<dim3(SS / 128, BB * HHN), 256, ATT_SMEM>>>(p_qkvh, p_atth);

    // 3) out-proj + residual(x) -> r1 fp32
    gemm_f16<false, true, false><<<dim3(EE / 128, MR / 256), 256, GSM_TOTAL>>>(
        p_atth, p_woh, b_out, x, p_r1, nullptr, EE, EE);

    // 4) LN1 -> x1 fp32 + fp16
    ln_kernel<true><<<MR, 256>>>(p_r1, g1, be1, p_x1, p_x1h);

    // 5) FFN up + ReLU -> h fp16
    gemm_f16<true, false, true><<<dim3(FFD / 128, MR / 256), 256, GSM_TOTAL>>>(
        p_x1h, p_w1h, b1, nullptr, nullptr, p_hh, FFD, EE);

    // 6) FFN down + residual(x1) -> r2 fp32
    gemm_f16<false, true, false><<<dim3(EE / 128, MR / 256), 256, GSM_TOTAL>>>(
        p_hh, p_w2h, b2, p_x1, p_r2, nullptr, EE, FFD);

    // 7) LN2 -> out
    ln_kernel<false><<<MR, 256>>>(p_r2, g2, be2, out, nullptr);
}